// round 11
// baseline (speedup 1.0000x reference)
#include <cuda_runtime.h>
#include <cuda_fp16.h>
#include <cstdint>

#define N_NODES 50000
#define N_EDGES 400000
#define D_IN    1024
#define D_HID   512
#define D_LAT   256

// Scratch (allocation-free rule: __device__ globals)
__device__ __half g_s1h[(size_t)N_NODES * D_HID];   // x @ W1 (fp16, gather src)
__device__ __half g_s2h[(size_t)N_NODES * D_LAT];   // hh @ W2 (fp16, gather src)
__device__ __half g_xh [(size_t)N_NODES * D_IN];    // x in fp16
__device__ __half g_hh [(size_t)N_NODES * D_HID];   // relu(agg1+b1) fp16
__device__ __half g_w1t[(size_t)D_HID * D_IN];      // W1^T fp16 [N][K]
__device__ __half g_w2t[(size_t)D_LAT * D_HID];     // W2^T fp16 [N][K]
// CSR-by-dst build
__device__ int   g_cnt [N_NODES];
__device__ int   g_off [N_NODES + 1];
__device__ int   g_cur [N_NODES];
__device__ int   g_psrc[N_EDGES];
__device__ float g_pw  [N_EDGES];

// ---------------------------------------------------------------------------
// fp16 mma.sync GEMM: CTA 128x256, BK=64, 3-stage, 512 thr, 64x32 warp tile,
// ldmatrix.x4, XOR swizzle chunk' = chunk ^ (row&7)
// ---------------------------------------------------------------------------
#define BM 128
#define BN 256
#define BK 64
#define STAGES 3
#define A_BYTES (BM * 128)
#define B_BYTES (BN * 128)
#define STAGE_BYTES (A_BYTES + B_BYTES)
#define SMEM_BYTES (STAGES * STAGE_BYTES)

__device__ __forceinline__ void hmma(float c[4], const uint32_t a[4],
                                     uint32_t b0, uint32_t b1) {
    asm volatile(
        "mma.sync.aligned.m16n8k16.row.col.f32.f16.f16.f32 "
        "{%0,%1,%2,%3}, {%4,%5,%6,%7}, {%8,%9}, {%0,%1,%2,%3};"
        : "+f"(c[0]), "+f"(c[1]), "+f"(c[2]), "+f"(c[3])
        : "r"(a[0]), "r"(a[1]), "r"(a[2]), "r"(a[3]), "r"(b0), "r"(b1));
}

__device__ __forceinline__ void ldsm4(uint32_t r[4], uint32_t addr) {
    asm volatile("ldmatrix.sync.aligned.m8n8.x4.shared.b16 {%0,%1,%2,%3}, [%4];"
                 : "=r"(r[0]), "=r"(r[1]), "=r"(r[2]), "=r"(r[3]) : "r"(addr));
}

__device__ __forceinline__ void cp16(uint32_t dst, const void* src, int sz) {
    asm volatile("cp.async.ca.shared.global [%0], [%1], 16, %2;\n"
                 :: "r"(dst), "l"(src), "r"(sz));
}
__device__ __forceinline__ void cp16u(uint32_t dst, const void* src) {
    asm volatile("cp.async.ca.shared.global [%0], [%1], 16;\n"
                 :: "r"(dst), "l"(src));
}

__global__ __launch_bounds__(512, 1)
void gemm_h(const __half* __restrict__ A, const __half* __restrict__ Bt,
            __half* __restrict__ C, int M, int N, int K) {
    extern __shared__ uint32_t smem[];
    const uint32_t sbase = (uint32_t)__cvta_generic_to_shared(smem);

    const int tid  = threadIdx.x;
    const int lane = tid & 31;
    const int wid  = tid >> 5;
    const int warp_m = wid & 1;
    const int warp_n = wid >> 1;
    const int qr = lane >> 2;
    const int qc = lane & 3;
    const int brow = blockIdx.x * BM;
    const int bcol = blockIdx.y * BN;

    const int laneA_row = lane & 15;
    const int laneA_h   = lane >> 4;
    const int laneB_row = (lane & 7) + ((lane >> 4) << 3);
    const int laneB_h   = (lane >> 3) & 1;
    const int rowA_base = warp_m * 64 + laneA_row;
    const int rowB_base = warp_n * 32 + laneB_row;

    float acc[4][4][4];
    #pragma unroll
    for (int i = 0; i < 4; i++)
        #pragma unroll
        for (int j = 0; j < 4; j++)
            #pragma unroll
            for (int k = 0; k < 4; k++) acc[i][j][k] = 0.f;

    auto load_stage = [&](int kt, int s) {
        const int kb = kt * BK;
        const uint32_t ab = sbase + (uint32_t)s * STAGE_BYTES;
        const uint32_t bb = ab + A_BYTES;
        #pragma unroll
        for (int t = 0; t < 2; t++) {
            int idx = tid + t * 512;
            int r = idx >> 3, c = idx & 7;
            int gr = brow + r;
            uint32_t dst = ab + r * 128 + ((c ^ (r & 7)) << 4);
            cp16(dst, A + (size_t)gr * K + kb + c * 8, (gr < M) ? 16 : 0);
        }
        #pragma unroll
        for (int t = 0; t < 4; t++) {
            int idx = tid + t * 512;
            int r = idx >> 3, c = idx & 7;
            uint32_t dst = bb + r * 128 + ((c ^ (r & 7)) << 4);
            cp16u(dst, Bt + (size_t)(bcol + r) * K + kb + c * 8);
        }
    };

    const int nk = K / BK;
    #pragma unroll
    for (int i = 0; i < STAGES - 1; i++) {
        load_stage(i, i);
        asm volatile("cp.async.commit_group;\n");
    }

    for (int kt = 0; kt < nk; kt++) {
        asm volatile("cp.async.wait_group %0;\n" :: "n"(STAGES - 2));
        __syncthreads();

        if (kt + STAGES - 1 < nk) load_stage(kt + STAGES - 1, (kt + STAGES - 1) % STAGES);
        asm volatile("cp.async.commit_group;\n");

        const int s = kt % STAGES;
        const uint32_t Ab = sbase + (uint32_t)s * STAGE_BYTES;
        const uint32_t Bb = Ab + A_BYTES;

        #pragma unroll
        for (int ks = 0; ks < 4; ks++) {
            uint32_t a[4][4], b[2][4];
            #pragma unroll
            for (int mt = 0; mt < 4; mt++) {
                int row = rowA_base + mt * 16;
                int ch  = ks * 2 + laneA_h;
                ldsm4(a[mt], Ab + row * 128 + ((ch ^ (row & 7)) << 4));
            }
            #pragma unroll
            for (int np = 0; np < 2; np++) {
                int row = rowB_base + np * 16;
                int ch  = ks * 2 + laneB_h;
                ldsm4(b[np], Bb + row * 128 + ((ch ^ (row & 7)) << 4));
            }
            #pragma unroll
            for (int mt = 0; mt < 4; mt++)
                #pragma unroll
                for (int nt = 0; nt < 4; nt++)
                    hmma(acc[mt][nt], a[mt], b[nt >> 1][(nt & 1) * 2],
                                             b[nt >> 1][(nt & 1) * 2 + 1]);
        }
    }

    #pragma unroll
    for (int mt = 0; mt < 4; mt++) {
        int r = brow + warp_m * 64 + mt * 16 + qr;
        #pragma unroll
        for (int nt = 0; nt < 4; nt++) {
            int c = bcol + warp_n * 32 + nt * 8 + qc * 2;
            if (r < M) {
                __half2 h = __floats2half2_rn(acc[mt][nt][0], acc[mt][nt][1]);
                *(__half2*)(C + (size_t)r * N + c) = h;
            }
            if (r + 8 < M) {
                __half2 h = __floats2half2_rn(acc[mt][nt][2], acc[mt][nt][3]);
                *(__half2*)(C + (size_t)(r + 8) * N + c) = h;
            }
        }
    }
}

// ---------------------------------------------------------------------------
// CSR-by-dst build
// ---------------------------------------------------------------------------
__global__ void hist_k(const int* __restrict__ ei, int* __restrict__ cnt) {
    int e = blockIdx.x * blockDim.x + threadIdx.x;
    if (e < N_EDGES) atomicAdd(&cnt[ei[N_EDGES + e]], 1);
}

__global__ __launch_bounds__(1024)
void scan_k(const int* __restrict__ cnt, int* __restrict__ off, int* __restrict__ cur) {
    __shared__ int sums[1024];
    const int t = threadIdx.x;
    const int CH = (N_NODES + 1023) / 1024;
    const int lo = t * CH;
    const int hi = min(lo + CH, N_NODES);
    int s = 0;
    for (int i = lo; i < hi; i++) s += cnt[i];
    sums[t] = s;
    __syncthreads();
    for (int d = 1; d < 1024; d <<= 1) {
        int v = (t >= d) ? sums[t - d] : 0;
        __syncthreads();
        sums[t] += v;
        __syncthreads();
    }
    int run = (t == 0) ? 0 : sums[t - 1];
    for (int i = lo; i < hi; i++) {
        off[i] = run; cur[i] = run;
        run += cnt[i];
    }
    if (t == 1023) off[N_NODES] = run;
}

__global__ void permute_k(const int* __restrict__ ei, const float* __restrict__ ew,
                          int* __restrict__ cur, int* __restrict__ psrc,
                          float* __restrict__ pw) {
    int e = blockIdx.x * blockDim.x + threadIdx.x;
    if (e >= N_EDGES) return;
    int dst = ei[N_EDGES + e];
    int pos = atomicAdd(&cur[dst], 1);
    psrc[pos] = ei[e];
    pw[pos]   = ew[e];
}

// ---------------------------------------------------------------------------
// Gather aggregation (warp per node), 4-edge unrolled, fused bias+relu.
// ---------------------------------------------------------------------------
__device__ __forceinline__ void acc8(float* acc, uint4 r, float w) {
    float2 f0 = __half22float2(*(__half2*)&r.x);
    float2 f1 = __half22float2(*(__half2*)&r.y);
    float2 f2 = __half22float2(*(__half2*)&r.z);
    float2 f3 = __half22float2(*(__half2*)&r.w);
    acc[0] += f0.x * w; acc[1] += f0.y * w;
    acc[2] += f1.x * w; acc[3] += f1.y * w;
    acc[4] += f2.x * w; acc[5] += f2.y * w;
    acc[6] += f3.x * w; acc[7] += f3.y * w;
}

__global__ __launch_bounds__(256)
void agg512_h(const __half* __restrict__ S, const int* __restrict__ off,
              const int* __restrict__ psrc, const float* __restrict__ pw,
              const float* __restrict__ bias, __half* __restrict__ outh) {
    const int node = (blockIdx.x * blockDim.x + threadIdx.x) >> 5;
    const int lane = threadIdx.x & 31;
    if (node >= N_NODES) return;
    const int e0 = off[node], e1 = off[node + 1];

    float acc[16];
    #pragma unroll
    for (int i = 0; i < 16; i++) acc[i] = 0.f;

    int e = e0;
    for (; e + 4 <= e1; e += 4) {
        int   s0 = psrc[e],   s1 = psrc[e+1], s2 = psrc[e+2], s3 = psrc[e+3];
        float w0 = pw[e],     w1 = pw[e+1],   w2 = pw[e+2],   w3 = pw[e+3];
        const uint4* r0 = (const uint4*)(S + (size_t)s0 * D_HID);
        const uint4* r1 = (const uint4*)(S + (size_t)s1 * D_HID);
        const uint4* r2 = (const uint4*)(S + (size_t)s2 * D_HID);
        const uint4* r3 = (const uint4*)(S + (size_t)s3 * D_HID);
        uint4 x0 = r0[lane],      y0 = r1[lane],      z0 = r2[lane],      u0 = r3[lane];
        uint4 x1 = r0[lane + 32], y1 = r1[lane + 32], z1 = r2[lane + 32], u1 = r3[lane + 32];
        acc8(acc, x0, w0); acc8(acc + 8, x1, w0);
        acc8(acc, y0, w1); acc8(acc + 8, y1, w1);
        acc8(acc, z0, w2); acc8(acc + 8, z1, w2);
        acc8(acc, u0, w3); acc8(acc + 8, u1, w3);
    }
    for (; e < e1; e++) {
        int s0 = psrc[e]; float w0 = pw[e];
        const uint4* r0 = (const uint4*)(S + (size_t)s0 * D_HID);
        uint4 x0 = r0[lane];
        uint4 x1 = r0[lane + 32];
        acc8(acc, x0, w0); acc8(acc + 8, x1, w0);
    }

    #pragma unroll
    for (int t = 0; t < 2; t++) {
        const int fb = (lane + t * 32) * 8;
        float4 b0 = *(const float4*)(bias + fb);
        float4 b1 = *(const float4*)(bias + fb + 4);
        float* a = acc + t * 8;
        __half2 h0 = __floats2half2_rn(fmaxf(a[0]+b0.x,0.f), fmaxf(a[1]+b0.y,0.f));
        __half2 h1 = __floats2half2_rn(fmaxf(a[2]+b0.z,0.f), fmaxf(a[3]+b0.w,0.f));
        __half2 h2 = __floats2half2_rn(fmaxf(a[4]+b1.x,0.f), fmaxf(a[5]+b1.y,0.f));
        __half2 h3 = __floats2half2_rn(fmaxf(a[6]+b1.z,0.f), fmaxf(a[7]+b1.w,0.f));
        uint4 o;
        o.x = *(uint32_t*)&h0; o.y = *(uint32_t*)&h1;
        o.z = *(uint32_t*)&h2; o.w = *(uint32_t*)&h3;
        *(uint4*)(outh + (size_t)node * D_HID + fb) = o;
    }
}

__global__ __launch_bounds__(256)
void agg256_f(const __half* __restrict__ S, const int* __restrict__ off,
              const int* __restrict__ psrc, const float* __restrict__ pw,
              const float* __restrict__ bias, float* __restrict__ outf) {
    const int node = (blockIdx.x * blockDim.x + threadIdx.x) >> 5;
    const int lane = threadIdx.x & 31;
    if (node >= N_NODES) return;
    const int e0 = off[node], e1 = off[node + 1];

    float acc[8];
    #pragma unroll
    for (int i = 0; i < 8; i++) acc[i] = 0.f;

    int e = e0;
    for (; e + 4 <= e1; e += 4) {
        int   s0 = psrc[e],   s1 = psrc[e+1], s2 = psrc[e+2], s3 = psrc[e+3];
        float w0 = pw[e],     w1 = pw[e+1],   w2 = pw[e+2],   w3 = pw[e+3];
        uint4 x = ((const uint4*)(S + (size_t)s0 * D_LAT))[lane];
        uint4 y = ((const uint4*)(S + (size_t)s1 * D_LAT))[lane];
        uint4 z = ((const uint4*)(S + (size_t)s2 * D_LAT))[lane];
        uint4 u = ((const uint4*)(S + (size_t)s3 * D_LAT))[lane];
        acc8(acc, x, w0); acc8(acc, y, w1); acc8(acc, z, w2); acc8(acc, u, w3);
    }
    for (; e < e1; e++) {
        uint4 x = ((const uint4*)(S + (size_t)psrc[e] * D_LAT))[lane];
        acc8(acc, x, pw[e]);
    }

    const int fb = lane * 8;
    float4 b0 = *(const float4*)(bias + fb);
    float4 b1 = *(const float4*)(bias + fb + 4);
    float4 o0 = make_float4(fmaxf(acc[0]+b0.x,0.f), fmaxf(acc[1]+b0.y,0.f),
                            fmaxf(acc[2]+b0.z,0.f), fmaxf(acc[3]+b0.w,0.f));
    float4 o1 = make_float4(fmaxf(acc[4]+b1.x,0.f), fmaxf(acc[5]+b1.y,0.f),
                            fmaxf(acc[6]+b1.z,0.f), fmaxf(acc[7]+b1.w,0.f));
    float* op = outf + (size_t)node * D_LAT + fb;
    *(float4*)op       = o0;
    *(float4*)(op + 4) = o1;
}

// ---------------------------------------------------------------------------
// staging
// ---------------------------------------------------------------------------
__global__ void to_half(const float4* __restrict__ in, uint2* __restrict__ out, int n4) {
    int i = blockIdx.x * blockDim.x + threadIdx.x;
    int stride = gridDim.x * blockDim.x;
    for (; i < n4; i += stride) {
        float4 v = in[i];
        __half2 h0 = __floats2half2_rn(v.x, v.y);
        __half2 h1 = __floats2half2_rn(v.z, v.w);
        out[i] = make_uint2(*(uint32_t*)&h0, *(uint32_t*)&h1);
    }
}

__global__ __launch_bounds__(256)
void transpose_h(const float* __restrict__ in, __half* __restrict__ out, int R, int Cc) {
    __shared__ float t[32][33];
    const int c0 = blockIdx.x * 32, r0 = blockIdx.y * 32;
    const int tx = threadIdx.x, ty = threadIdx.y;
    #pragma unroll
    for (int i = ty; i < 32; i += 8)
        t[i][tx] = in[(size_t)(r0 + i) * Cc + c0 + tx];
    __syncthreads();
    #pragma unroll
    for (int i = ty; i < 32; i += 8)
        out[(size_t)(c0 + i) * R + r0 + tx] = __float2half(t[tx][i]);
}

// ---------------------------------------------------------------------------
// launch — wave-aligned overlap:
//   s2: CSR + W2^T                       (joins before agg512)
//   s3: W1^T ; to_half chunk1 (after c0) (GEMM1 chunk1 waits it)
//   main: to_half chunk0 ; GEMM1 c0 ; GEMM1 c1 ; agg512 ; GEMM2 ; agg256
//   GEMM1 chunks: 196+195 M-blocks -> 3+3 waves (same as full grid's 6)
// ---------------------------------------------------------------------------
#define CH_ROWS (196 * BM)      // 25088 rows in chunk 0

extern "C" void kernel_launch(void* const* d_in, const int* in_sizes, int n_in,
                              void* d_out, int out_size) {
    const float* x  = (const float*)d_in[0];
    const int*   ei = (const int*)  d_in[1];
    const float* ew = (const float*)d_in[2];
    const float* W1 = (const float*)d_in[3];
    const float* b1 = (const float*)d_in[4];
    const float* W2 = (const float*)d_in[5];
    const float* b2 = (const float*)d_in[6];
    float* out = (float*)d_out;

    __half *s1h, *s2h, *xh, *hh, *w1t, *w2t;
    int *cnt, *off, *cur, *psrc;
    float *pw;
    cudaGetSymbolAddress((void**)&s1h,  g_s1h);
    cudaGetSymbolAddress((void**)&s2h,  g_s2h);
    cudaGetSymbolAddress((void**)&xh,   g_xh);
    cudaGetSymbolAddress((void**)&hh,   g_hh);
    cudaGetSymbolAddress((void**)&w1t,  g_w1t);
    cudaGetSymbolAddress((void**)&w2t,  g_w2t);
    cudaGetSymbolAddress((void**)&cnt,  g_cnt);
    cudaGetSymbolAddress((void**)&off,  g_off);
    cudaGetSymbolAddress((void**)&cur,  g_cur);
    cudaGetSymbolAddress((void**)&psrc, g_psrc);
    cudaGetSymbolAddress((void**)&pw,   g_pw);

    static cudaStream_t s2 = nullptr, s3 = nullptr;
    static cudaEvent_t evA = nullptr, evB = nullptr, evW = nullptr;
    static cudaEvent_t evC0 = nullptr, evT1 = nullptr;
    static bool init_done = false;
    if (!init_done) {
        cudaFuncSetAttribute(gemm_h, cudaFuncAttributeMaxDynamicSharedMemorySize,
                             SMEM_BYTES);
        cudaStreamCreateWithFlags(&s2, cudaStreamNonBlocking);
        cudaStreamCreateWithFlags(&s3, cudaStreamNonBlocking);
        cudaEventCreateWithFlags(&evA,  cudaEventDisableTiming);
        cudaEventCreateWithFlags(&evB,  cudaEventDisableTiming);
        cudaEventCreateWithFlags(&evW,  cudaEventDisableTiming);
        cudaEventCreateWithFlags(&evC0, cudaEventDisableTiming);
        cudaEventCreateWithFlags(&evT1, cudaEventDisableTiming);
        init_done = true;
    }

    // fork
    cudaEventRecord(evA, 0);
    cudaStreamWaitEvent(s2, evA, 0);
    cudaStreamWaitEvent(s3, evA, 0);

    // s2: CSR build + W2^T
    cudaMemsetAsync(cnt, 0, N_NODES * sizeof(int), s2);
    hist_k<<<(N_EDGES + 255) / 256, 256, 0, s2>>>(ei, cnt);
    scan_k<<<1, 1024, 0, s2>>>(cnt, off, cur);
    permute_k<<<(N_EDGES + 255) / 256, 256, 0, s2>>>(ei, ew, cur, psrc, pw);
    transpose_h<<<dim3(D_LAT / 32, D_HID / 32), dim3(32, 8), 0, s2>>>(W2, w2t,
                                                                      D_HID, D_LAT);
    cudaEventRecord(evB, s2);

    // s3: W1^T (overlaps to_half chunk0 on main)
    transpose_h<<<dim3(D_HID / 32, D_IN / 32), dim3(32, 8), 0, s3>>>(W1, w1t,
                                                                     D_IN, D_HID);
    cudaEventRecord(evW, s3);

    // main: to_half chunk0
    to_half<<<4096, 256>>>((const float4*)x, (uint2*)xh, CH_ROWS * (D_IN / 4));
    cudaEventRecord(evC0, 0);

    // s3: to_half chunk1 after chunk0 (serialized DRAM use; overlaps GEMM1 c0)
    cudaStreamWaitEvent(s3, evC0, 0);
    {
        const int rows1 = N_NODES - CH_ROWS;
        to_half<<<4096, 256, 0, s3>>>(
            (const float4*)(x + (size_t)CH_ROWS * D_IN),
            (uint2*)(xh + (size_t)CH_ROWS * D_IN), rows1 * (D_IN / 4));
        cudaEventRecord(evT1, s3);
    }

    // main: GEMM1 chunk0 (196 blocks, 3 waves)
    cudaStreamWaitEvent(0, evW, 0);
    gemm_h<<<dim3(CH_ROWS / BM, D_HID / BN), 512, SMEM_BYTES>>>(
        xh, w1t, s1h, CH_ROWS, D_HID, D_IN);

    // main: GEMM1 chunk1 (195 blocks, 3 waves)
    cudaStreamWaitEvent(0, evT1, 0);
    {
        const int rows1 = N_NODES - CH_ROWS;
        gemm_h<<<dim3((rows1 + BM - 1) / BM, D_HID / BN), 512, SMEM_BYTES>>>(
            xh + (size_t)CH_ROWS * D_IN, w1t, s1h + (size_t)CH_ROWS * D_HID,
            rows1, D_HID, D_IN);
    }

    // join CSR, then layer-1 gather (full)
    cudaStreamWaitEvent(0, evB, 0);
    const int agg_blocks = (N_NODES * 32 + 255) / 256;
    agg512_h<<<agg_blocks, 256>>>(s1h, off, psrc, pw, b1, hh);

    // Layer 2 (full grids)
    gemm_h<<<dim3((N_NODES + BM - 1) / BM, D_LAT / BN), 512, SMEM_BYTES>>>(
        hh, w2t, s2h, N_NODES, D_LAT, D_HID);
    agg256_f<<<agg_blocks, 256>>>(s2h, off, psrc, pw, b2, out);
}

// round 12
// speedup vs baseline: 1.3803x; 1.3803x over previous
#include <cuda_runtime.h>
#include <cuda_fp16.h>
#include <cstdint>

#define N_NODES 50000
#define N_EDGES 400000
#define D_IN    1024
#define D_HID   512
#define D_LAT   256

// Scratch (allocation-free rule: __device__ globals)
__device__ __half g_s1h[(size_t)N_NODES * D_HID];   // x @ W1 (fp16, gather src)
__device__ __half g_s2h[(size_t)N_NODES * D_LAT];   // hh @ W2 (fp16, gather src)
__device__ __half g_xh [(size_t)N_NODES * D_IN];    // x in fp16
__device__ __half g_hh [(size_t)N_NODES * D_HID];   // relu(agg1+b1) fp16
__device__ __half g_w1t[(size_t)D_HID * D_IN];      // W1^T fp16 [N][K]
__device__ __half g_w2t[(size_t)D_LAT * D_HID];     // W2^T fp16 [N][K]
// CSR-by-dst build
__device__ int   g_cnt [N_NODES];
__device__ int   g_off [N_NODES + 1];
__device__ int   g_cur [N_NODES];
__device__ int   g_psrc[N_EDGES];
__device__ float g_pw  [N_EDGES];

// ---------------------------------------------------------------------------
// fp16 mma.sync GEMM: CTA 128x256, BK=64, 3-stage, 512 thr, 64x32 warp tile,
// ldmatrix.x4, XOR swizzle chunk' = chunk ^ (row&7)
// ---------------------------------------------------------------------------
#define BM 128
#define BN 256
#define BK 64
#define STAGES 3
#define A_BYTES (BM * 128)
#define B_BYTES (BN * 128)
#define STAGE_BYTES (A_BYTES + B_BYTES)
#define SMEM_BYTES (STAGES * STAGE_BYTES)

__device__ __forceinline__ void hmma(float c[4], const uint32_t a[4],
                                     uint32_t b0, uint32_t b1) {
    asm volatile(
        "mma.sync.aligned.m16n8k16.row.col.f32.f16.f16.f32 "
        "{%0,%1,%2,%3}, {%4,%5,%6,%7}, {%8,%9}, {%0,%1,%2,%3};"
        : "+f"(c[0]), "+f"(c[1]), "+f"(c[2]), "+f"(c[3])
        : "r"(a[0]), "r"(a[1]), "r"(a[2]), "r"(a[3]), "r"(b0), "r"(b1));
}

__device__ __forceinline__ void ldsm4(uint32_t r[4], uint32_t addr) {
    asm volatile("ldmatrix.sync.aligned.m8n8.x4.shared.b16 {%0,%1,%2,%3}, [%4];"
                 : "=r"(r[0]), "=r"(r[1]), "=r"(r[2]), "=r"(r[3]) : "r"(addr));
}

__device__ __forceinline__ void cp16(uint32_t dst, const void* src, int sz) {
    asm volatile("cp.async.ca.shared.global [%0], [%1], 16, %2;\n"
                 :: "r"(dst), "l"(src), "r"(sz));
}
__device__ __forceinline__ void cp16u(uint32_t dst, const void* src) {
    asm volatile("cp.async.ca.shared.global [%0], [%1], 16;\n"
                 :: "r"(dst), "l"(src));
}

__global__ __launch_bounds__(512, 1)
void gemm_h(const __half* __restrict__ A, const __half* __restrict__ Bt,
            __half* __restrict__ C, int M, int N, int K) {
    extern __shared__ uint32_t smem[];
    const uint32_t sbase = (uint32_t)__cvta_generic_to_shared(smem);

    const int tid  = threadIdx.x;
    const int lane = tid & 31;
    const int wid  = tid >> 5;
    const int warp_m = wid & 1;
    const int warp_n = wid >> 1;
    const int qr = lane >> 2;
    const int qc = lane & 3;
    const int brow = blockIdx.x * BM;
    const int bcol = blockIdx.y * BN;

    const int laneA_row = lane & 15;
    const int laneA_h   = lane >> 4;
    const int laneB_row = (lane & 7) + ((lane >> 4) << 3);
    const int laneB_h   = (lane >> 3) & 1;
    const int rowA_base = warp_m * 64 + laneA_row;
    const int rowB_base = warp_n * 32 + laneB_row;

    float acc[4][4][4];
    #pragma unroll
    for (int i = 0; i < 4; i++)
        #pragma unroll
        for (int j = 0; j < 4; j++)
            #pragma unroll
            for (int k = 0; k < 4; k++) acc[i][j][k] = 0.f;

    auto load_stage = [&](int kt, int s) {
        const int kb = kt * BK;
        const uint32_t ab = sbase + (uint32_t)s * STAGE_BYTES;
        const uint32_t bb = ab + A_BYTES;
        #pragma unroll
        for (int t = 0; t < 2; t++) {
            int idx = tid + t * 512;
            int r = idx >> 3, c = idx & 7;
            int gr = brow + r;
            uint32_t dst = ab + r * 128 + ((c ^ (r & 7)) << 4);
            cp16(dst, A + (size_t)gr * K + kb + c * 8, (gr < M) ? 16 : 0);
        }
        #pragma unroll
        for (int t = 0; t < 4; t++) {
            int idx = tid + t * 512;
            int r = idx >> 3, c = idx & 7;
            uint32_t dst = bb + r * 128 + ((c ^ (r & 7)) << 4);
            cp16u(dst, Bt + (size_t)(bcol + r) * K + kb + c * 8);
        }
    };

    const int nk = K / BK;
    #pragma unroll
    for (int i = 0; i < STAGES - 1; i++) {
        load_stage(i, i);
        asm volatile("cp.async.commit_group;\n");
    }

    for (int kt = 0; kt < nk; kt++) {
        asm volatile("cp.async.wait_group %0;\n" :: "n"(STAGES - 2));
        __syncthreads();

        if (kt + STAGES - 1 < nk) load_stage(kt + STAGES - 1, (kt + STAGES - 1) % STAGES);
        asm volatile("cp.async.commit_group;\n");

        const int s = kt % STAGES;
        const uint32_t Ab = sbase + (uint32_t)s * STAGE_BYTES;
        const uint32_t Bb = Ab + A_BYTES;

        #pragma unroll
        for (int ks = 0; ks < 4; ks++) {
            uint32_t a[4][4], b[2][4];
            #pragma unroll
            for (int mt = 0; mt < 4; mt++) {
                int row = rowA_base + mt * 16;
                int ch  = ks * 2 + laneA_h;
                ldsm4(a[mt], Ab + row * 128 + ((ch ^ (row & 7)) << 4));
            }
            #pragma unroll
            for (int np = 0; np < 2; np++) {
                int row = rowB_base + np * 16;
                int ch  = ks * 2 + laneB_h;
                ldsm4(b[np], Bb + row * 128 + ((ch ^ (row & 7)) << 4));
            }
            #pragma unroll
            for (int mt = 0; mt < 4; mt++)
                #pragma unroll
                for (int nt = 0; nt < 4; nt++)
                    hmma(acc[mt][nt], a[mt], b[nt >> 1][(nt & 1) * 2],
                                             b[nt >> 1][(nt & 1) * 2 + 1]);
        }
    }

    #pragma unroll
    for (int mt = 0; mt < 4; mt++) {
        int r = brow + warp_m * 64 + mt * 16 + qr;
        #pragma unroll
        for (int nt = 0; nt < 4; nt++) {
            int c = bcol + warp_n * 32 + nt * 8 + qc * 2;
            if (r < M) {
                __half2 h = __floats2half2_rn(acc[mt][nt][0], acc[mt][nt][1]);
                *(__half2*)(C + (size_t)r * N + c) = h;
            }
            if (r + 8 < M) {
                __half2 h = __floats2half2_rn(acc[mt][nt][2], acc[mt][nt][3]);
                *(__half2*)(C + (size_t)(r + 8) * N + c) = h;
            }
        }
    }
}

// ---------------------------------------------------------------------------
// CSR-by-dst build
// ---------------------------------------------------------------------------
__global__ void hist_k(const int* __restrict__ ei, int* __restrict__ cnt) {
    int e = blockIdx.x * blockDim.x + threadIdx.x;
    if (e < N_EDGES) atomicAdd(&cnt[ei[N_EDGES + e]], 1);
}

__global__ __launch_bounds__(1024)
void scan_k(const int* __restrict__ cnt, int* __restrict__ off, int* __restrict__ cur) {
    __shared__ int sums[1024];
    const int t = threadIdx.x;
    const int CH = (N_NODES + 1023) / 1024;
    const int lo = t * CH;
    const int hi = min(lo + CH, N_NODES);
    int s = 0;
    for (int i = lo; i < hi; i++) s += cnt[i];
    sums[t] = s;
    __syncthreads();
    for (int d = 1; d < 1024; d <<= 1) {
        int v = (t >= d) ? sums[t - d] : 0;
        __syncthreads();
        sums[t] += v;
        __syncthreads();
    }
    int run = (t == 0) ? 0 : sums[t - 1];
    for (int i = lo; i < hi; i++) {
        off[i] = run; cur[i] = run;
        run += cnt[i];
    }
    if (t == 1023) off[N_NODES] = run;
}

__global__ void permute_k(const int* __restrict__ ei, const float* __restrict__ ew,
                          int* __restrict__ cur, int* __restrict__ psrc,
                          float* __restrict__ pw) {
    int e = blockIdx.x * blockDim.x + threadIdx.x;
    if (e >= N_EDGES) return;
    int dst = ei[N_EDGES + e];
    int pos = atomicAdd(&cur[dst], 1);
    psrc[pos] = ei[e];
    pw[pos]   = ew[e];
}

// ---------------------------------------------------------------------------
// Gather aggregation, 4-edge unrolled, fused bias+relu.
// agg512: TWO warps per node (each owns 256 of 512 features).
// agg256: one warp per node.
// ---------------------------------------------------------------------------
__device__ __forceinline__ void acc8(float* acc, uint4 r, float w) {
    float2 f0 = __half22float2(*(__half2*)&r.x);
    float2 f1 = __half22float2(*(__half2*)&r.y);
    float2 f2 = __half22float2(*(__half2*)&r.z);
    float2 f3 = __half22float2(*(__half2*)&r.w);
    acc[0] += f0.x * w; acc[1] += f0.y * w;
    acc[2] += f1.x * w; acc[3] += f1.y * w;
    acc[4] += f2.x * w; acc[5] += f2.y * w;
    acc[6] += f3.x * w; acc[7] += f3.y * w;
}

__global__ __launch_bounds__(256)
void agg512_h(const __half* __restrict__ S, const int* __restrict__ off,
              const int* __restrict__ psrc, const float* __restrict__ pw,
              const float* __restrict__ bias, __half* __restrict__ outh) {
    const int gidx = blockIdx.x * blockDim.x + threadIdx.x;
    const int node = gidx >> 6;                    // 64 threads (2 warps) per node
    const int lane = threadIdx.x & 31;
    const int half = (threadIdx.x >> 5) & 1;       // which 256-feature half
    if (node >= N_NODES) return;
    const int e0 = off[node], e1 = off[node + 1];
    const int col = lane + half * 32;              // uint4 column in row (64 total)

    float acc[8];
    #pragma unroll
    for (int i = 0; i < 8; i++) acc[i] = 0.f;

    int e = e0;
    for (; e + 4 <= e1; e += 4) {
        int   s0 = psrc[e],   s1 = psrc[e+1], s2 = psrc[e+2], s3 = psrc[e+3];
        float w0 = pw[e],     w1 = pw[e+1],   w2 = pw[e+2],   w3 = pw[e+3];
        uint4 x = ((const uint4*)(S + (size_t)s0 * D_HID))[col];
        uint4 y = ((const uint4*)(S + (size_t)s1 * D_HID))[col];
        uint4 z = ((const uint4*)(S + (size_t)s2 * D_HID))[col];
        uint4 u = ((const uint4*)(S + (size_t)s3 * D_HID))[col];
        acc8(acc, x, w0); acc8(acc, y, w1); acc8(acc, z, w2); acc8(acc, u, w3);
    }
    for (; e < e1; e++) {
        uint4 x = ((const uint4*)(S + (size_t)psrc[e] * D_HID))[col];
        acc8(acc, x, pw[e]);
    }

    const int fb = col * 8;
    float4 b0 = *(const float4*)(bias + fb);
    float4 b1 = *(const float4*)(bias + fb + 4);
    __half2 h0 = __floats2half2_rn(fmaxf(acc[0]+b0.x,0.f), fmaxf(acc[1]+b0.y,0.f));
    __half2 h1 = __floats2half2_rn(fmaxf(acc[2]+b0.z,0.f), fmaxf(acc[3]+b0.w,0.f));
    __half2 h2 = __floats2half2_rn(fmaxf(acc[4]+b1.x,0.f), fmaxf(acc[5]+b1.y,0.f));
    __half2 h3 = __floats2half2_rn(fmaxf(acc[6]+b1.z,0.f), fmaxf(acc[7]+b1.w,0.f));
    uint4 o;
    o.x = *(uint32_t*)&h0; o.y = *(uint32_t*)&h1;
    o.z = *(uint32_t*)&h2; o.w = *(uint32_t*)&h3;
    *(uint4*)(outh + (size_t)node * D_HID + fb) = o;
}

__global__ __launch_bounds__(256)
void agg256_f(const __half* __restrict__ S, const int* __restrict__ off,
              const int* __restrict__ psrc, const float* __restrict__ pw,
              const float* __restrict__ bias, float* __restrict__ outf) {
    const int node = (blockIdx.x * blockDim.x + threadIdx.x) >> 5;
    const int lane = threadIdx.x & 31;
    if (node >= N_NODES) return;
    const int e0 = off[node], e1 = off[node + 1];

    float acc[8];
    #pragma unroll
    for (int i = 0; i < 8; i++) acc[i] = 0.f;

    int e = e0;
    for (; e + 4 <= e1; e += 4) {
        int   s0 = psrc[e],   s1 = psrc[e+1], s2 = psrc[e+2], s3 = psrc[e+3];
        float w0 = pw[e],     w1 = pw[e+1],   w2 = pw[e+2],   w3 = pw[e+3];
        uint4 x = ((const uint4*)(S + (size_t)s0 * D_LAT))[lane];
        uint4 y = ((const uint4*)(S + (size_t)s1 * D_LAT))[lane];
        uint4 z = ((const uint4*)(S + (size_t)s2 * D_LAT))[lane];
        uint4 u = ((const uint4*)(S + (size_t)s3 * D_LAT))[lane];
        acc8(acc, x, w0); acc8(acc, y, w1); acc8(acc, z, w2); acc8(acc, u, w3);
    }
    for (; e < e1; e++) {
        uint4 x = ((const uint4*)(S + (size_t)psrc[e] * D_LAT))[lane];
        acc8(acc, x, pw[e]);
    }

    const int fb = lane * 8;
    float4 b0 = *(const float4*)(bias + fb);
    float4 b1 = *(const float4*)(bias + fb + 4);
    float4 o0 = make_float4(fmaxf(acc[0]+b0.x,0.f), fmaxf(acc[1]+b0.y,0.f),
                            fmaxf(acc[2]+b0.z,0.f), fmaxf(acc[3]+b0.w,0.f));
    float4 o1 = make_float4(fmaxf(acc[4]+b1.x,0.f), fmaxf(acc[5]+b1.y,0.f),
                            fmaxf(acc[6]+b1.z,0.f), fmaxf(acc[7]+b1.w,0.f));
    float* op = outf + (size_t)node * D_LAT + fb;
    *(float4*)op       = o0;
    *(float4*)(op + 4) = o1;
}

// ---------------------------------------------------------------------------
// staging
// ---------------------------------------------------------------------------
__global__ void to_half(const float4* __restrict__ in, uint2* __restrict__ out, int n4) {
    int i = blockIdx.x * blockDim.x + threadIdx.x;
    int stride = gridDim.x * blockDim.x;
    for (; i < n4; i += stride) {
        float4 v = in[i];
        __half2 h0 = __floats2half2_rn(v.x, v.y);
        __half2 h1 = __floats2half2_rn(v.z, v.w);
        out[i] = make_uint2(*(uint32_t*)&h0, *(uint32_t*)&h1);
    }
}

__global__ __launch_bounds__(256)
void transpose_h(const float* __restrict__ in, __half* __restrict__ out, int R, int Cc) {
    __shared__ float t[32][33];
    const int c0 = blockIdx.x * 32, r0 = blockIdx.y * 32;
    const int tx = threadIdx.x, ty = threadIdx.y;
    #pragma unroll
    for (int i = ty; i < 32; i += 8)
        t[i][tx] = in[(size_t)(r0 + i) * Cc + c0 + tx];
    __syncthreads();
    #pragma unroll
    for (int i = ty; i < 32; i += 8)
        out[(size_t)(c0 + i) * R + r0 + tx] = __float2half(t[tx][i]);
}

// ---------------------------------------------------------------------------
// launch — R9 topology (proven): single serial main chain, only the SM-light
// CSR branch forked. No GEMM chunking (1 CTA/SM GEMM fills the machine; fake
// concurrency only adds serialization — R10/R11 lesson).
// ---------------------------------------------------------------------------
extern "C" void kernel_launch(void* const* d_in, const int* in_sizes, int n_in,
                              void* d_out, int out_size) {
    const float* x  = (const float*)d_in[0];
    const int*   ei = (const int*)  d_in[1];
    const float* ew = (const float*)d_in[2];
    const float* W1 = (const float*)d_in[3];
    const float* b1 = (const float*)d_in[4];
    const float* W2 = (const float*)d_in[5];
    const float* b2 = (const float*)d_in[6];
    float* out = (float*)d_out;

    __half *s1h, *s2h, *xh, *hh, *w1t, *w2t;
    int *cnt, *off, *cur, *psrc;
    float *pw;
    cudaGetSymbolAddress((void**)&s1h,  g_s1h);
    cudaGetSymbolAddress((void**)&s2h,  g_s2h);
    cudaGetSymbolAddress((void**)&xh,   g_xh);
    cudaGetSymbolAddress((void**)&hh,   g_hh);
    cudaGetSymbolAddress((void**)&w1t,  g_w1t);
    cudaGetSymbolAddress((void**)&w2t,  g_w2t);
    cudaGetSymbolAddress((void**)&cnt,  g_cnt);
    cudaGetSymbolAddress((void**)&off,  g_off);
    cudaGetSymbolAddress((void**)&cur,  g_cur);
    cudaGetSymbolAddress((void**)&psrc, g_psrc);
    cudaGetSymbolAddress((void**)&pw,   g_pw);

    static cudaStream_t s2 = nullptr;
    static cudaEvent_t evA = nullptr, evB = nullptr;
    static bool init_done = false;
    if (!init_done) {
        cudaFuncSetAttribute(gemm_h, cudaFuncAttributeMaxDynamicSharedMemorySize,
                             SMEM_BYTES);
        cudaStreamCreateWithFlags(&s2, cudaStreamNonBlocking);
        cudaEventCreateWithFlags(&evA, cudaEventDisableTiming);
        cudaEventCreateWithFlags(&evB, cudaEventDisableTiming);
        init_done = true;
    }

    const int mblocks = (N_NODES + BM - 1) / BM;        // 391

    // fork: side branch (CSR build + W2 transpose) on s2
    cudaEventRecord(evA, 0);
    cudaStreamWaitEvent(s2, evA, 0);
    cudaMemsetAsync(cnt, 0, N_NODES * sizeof(int), s2);
    hist_k<<<(N_EDGES + 255) / 256, 256, 0, s2>>>(ei, cnt);
    scan_k<<<1, 1024, 0, s2>>>(cnt, off, cur);
    permute_k<<<(N_EDGES + 255) / 256, 256, 0, s2>>>(ei, ew, cur, psrc, pw);
    transpose_h<<<dim3(D_LAT / 32, D_HID / 32), dim3(32, 8), 0, s2>>>(W2, w2t,
                                                                      D_HID, D_LAT);
    cudaEventRecord(evB, s2);

    // main branch: staging + GEMM1
    to_half<<<4096, 256>>>((const float4*)x, (uint2*)xh, N_NODES * D_IN / 4);
    transpose_h<<<dim3(D_HID / 32, D_IN / 32), dim3(32, 8)>>>(W1, w1t, D_IN, D_HID);
    gemm_h<<<dim3(mblocks, D_HID / BN), 512, SMEM_BYTES>>>(xh, w1t, s1h,
                                                           N_NODES, D_HID, D_IN);

    // join: agg needs CSR arrays; 2 warps per node
    cudaStreamWaitEvent(0, evB, 0);
    const int agg512_blocks = (N_NODES * 64 + 255) / 256;   // 12500
    agg512_h<<<agg512_blocks, 256>>>(s1h, off, psrc, pw, b1, hh);

    // Layer 2
    gemm_h<<<dim3(mblocks, D_LAT / BN), 512, SMEM_BYTES>>>(hh, w2t, s2h,
                                                           N_NODES, D_LAT, D_HID);
    const int agg256_blocks = (N_NODES * 32 + 255) / 256;   // 6250
    agg256_f<<<agg256_blocks, 256>>>(s2h, off, psrc, pw, b2, out);
}

// round 13
// speedup vs baseline: 1.4227x; 1.0307x over previous
#include <cuda_runtime.h>
#include <cuda_fp16.h>
#include <cstdint>

#define N_NODES 50000
#define N_EDGES 400000
#define D_IN    1024
#define D_HID   512
#define D_LAT   256

// Scratch (allocation-free rule: __device__ globals)
__device__ __half g_s1h[(size_t)N_NODES * D_HID];   // x @ W1 (fp16, gather src)
__device__ __half g_s2h[(size_t)N_NODES * D_LAT];   // hh @ W2 (fp16, gather src)
__device__ __half g_xh [(size_t)N_NODES * D_IN];    // x in fp16
__device__ __half g_hh [(size_t)N_NODES * D_HID];   // relu(agg1+b1) fp16
__device__ __half g_w1t[(size_t)D_HID * D_IN];      // W1^T fp16 [N][K]
__device__ __half g_w2t[(size_t)D_LAT * D_HID];     // W2^T fp16 [N][K]
// CSR-by-dst build
__device__ int   g_cnt [N_NODES];
__device__ int   g_off [N_NODES + 1];
__device__ int   g_cur [N_NODES];
__device__ int   g_psrc[N_EDGES];
__device__ float g_pw  [N_EDGES];

// ---------------------------------------------------------------------------
// fp16 mma.sync GEMM: CTA 128x128, BK=64, 3-stage cp.async, 256 thr (8 warps,
// 64x32 warp tile), ldmatrix.x4, XOR swizzle chunk' = chunk ^ (row&7).
// 96KB smem/CTA -> TWO CTAs per SM (independent barriers cover each other's
// sync/ldsm stalls; same 16 warps/SM as before but decoupled).
// ---------------------------------------------------------------------------
#define BM 128
#define BN 128
#define BK 64
#define STAGES 3
#define A_BYTES (BM * 128)                 // 16384
#define B_BYTES (BN * 128)                 // 16384
#define STAGE_BYTES (A_BYTES + B_BYTES)    // 32768
#define SMEM_BYTES (STAGES * STAGE_BYTES)  // 98304

__device__ __forceinline__ void hmma(float c[4], const uint32_t a[4],
                                     uint32_t b0, uint32_t b1) {
    asm volatile(
        "mma.sync.aligned.m16n8k16.row.col.f32.f16.f16.f32 "
        "{%0,%1,%2,%3}, {%4,%5,%6,%7}, {%8,%9}, {%0,%1,%2,%3};"
        : "+f"(c[0]), "+f"(c[1]), "+f"(c[2]), "+f"(c[3])
        : "r"(a[0]), "r"(a[1]), "r"(a[2]), "r"(a[3]), "r"(b0), "r"(b1));
}

__device__ __forceinline__ void ldsm4(uint32_t r[4], uint32_t addr) {
    asm volatile("ldmatrix.sync.aligned.m8n8.x4.shared.b16 {%0,%1,%2,%3}, [%4];"
                 : "=r"(r[0]), "=r"(r[1]), "=r"(r[2]), "=r"(r[3]) : "r"(addr));
}

__device__ __forceinline__ void cp16(uint32_t dst, const void* src, int sz) {
    asm volatile("cp.async.ca.shared.global [%0], [%1], 16, %2;\n"
                 :: "r"(dst), "l"(src), "r"(sz));
}
__device__ __forceinline__ void cp16u(uint32_t dst, const void* src) {
    asm volatile("cp.async.ca.shared.global [%0], [%1], 16;\n"
                 :: "r"(dst), "l"(src));
}

__global__ __launch_bounds__(256, 2)
void gemm_h(const __half* __restrict__ A, const __half* __restrict__ Bt,
            __half* __restrict__ C, int M, int N, int K) {
    extern __shared__ uint32_t smem[];
    const uint32_t sbase = (uint32_t)__cvta_generic_to_shared(smem);

    const int tid  = threadIdx.x;
    const int lane = tid & 31;
    const int wid  = tid >> 5;
    const int warp_m = wid & 1;      // 2 warps along M (64 rows)
    const int warp_n = wid >> 1;     // 4 warps along N (32 cols)
    const int qr = lane >> 2;
    const int qc = lane & 3;
    const int brow = blockIdx.x * BM;
    const int bcol = blockIdx.y * BN;

    const int laneA_row = lane & 15;
    const int laneA_h   = lane >> 4;
    const int laneB_row = (lane & 7) + ((lane >> 4) << 3);
    const int laneB_h   = (lane >> 3) & 1;
    const int rowA_base = warp_m * 64 + laneA_row;
    const int rowB_base = warp_n * 32 + laneB_row;

    float acc[4][4][4];
    #pragma unroll
    for (int i = 0; i < 4; i++)
        #pragma unroll
        for (int j = 0; j < 4; j++)
            #pragma unroll
            for (int k = 0; k < 4; k++) acc[i][j][k] = 0.f;

    // stage loader: A 128 rows x 8 chunks(16B), B 128 rows x 8 chunks
    auto load_stage = [&](int kt, int s) {
        const int kb = kt * BK;
        const uint32_t ab = sbase + (uint32_t)s * STAGE_BYTES;
        const uint32_t bb = ab + A_BYTES;
        #pragma unroll
        for (int t = 0; t < 4; t++) {                    // A: 1024 chunks
            int idx = tid + t * 256;
            int r = idx >> 3, c = idx & 7;
            int gr = brow + r;
            uint32_t dst = ab + r * 128 + ((c ^ (r & 7)) << 4);
            cp16(dst, A + (size_t)gr * K + kb + c * 8, (gr < M) ? 16 : 0);
        }
        #pragma unroll
        for (int t = 0; t < 4; t++) {                    // B: 1024 chunks
            int idx = tid + t * 256;
            int r = idx >> 3, c = idx & 7;
            uint32_t dst = bb + r * 128 + ((c ^ (r & 7)) << 4);
            cp16u(dst, Bt + (size_t)(bcol + r) * K + kb + c * 8);
        }
    };

    const int nk = K / BK;
    #pragma unroll
    for (int i = 0; i < STAGES - 1; i++) {
        load_stage(i, i);
        asm volatile("cp.async.commit_group;\n");
    }

    for (int kt = 0; kt < nk; kt++) {
        asm volatile("cp.async.wait_group %0;\n" :: "n"(STAGES - 2));
        __syncthreads();

        if (kt + STAGES - 1 < nk) load_stage(kt + STAGES - 1, (kt + STAGES - 1) % STAGES);
        asm volatile("cp.async.commit_group;\n");

        const int s = kt % STAGES;
        const uint32_t Ab = sbase + (uint32_t)s * STAGE_BYTES;
        const uint32_t Bb = Ab + A_BYTES;

        #pragma unroll
        for (int ks = 0; ks < 4; ks++) {
            uint32_t a[4][4], b[2][4];
            #pragma unroll
            for (int mt = 0; mt < 4; mt++) {
                int row = rowA_base + mt * 16;
                int ch  = ks * 2 + laneA_h;
                ldsm4(a[mt], Ab + row * 128 + ((ch ^ (row & 7)) << 4));
            }
            #pragma unroll
            for (int np = 0; np < 2; np++) {
                int row = rowB_base + np * 16;
                int ch  = ks * 2 + laneB_h;
                ldsm4(b[np], Bb + row * 128 + ((ch ^ (row & 7)) << 4));
            }
            #pragma unroll
            for (int mt = 0; mt < 4; mt++)
                #pragma unroll
                for (int nt = 0; nt < 4; nt++)
                    hmma(acc[mt][nt], a[mt], b[nt >> 1][(nt & 1) * 2],
                                             b[nt >> 1][(nt & 1) * 2 + 1]);
        }
        // no trailing sync: next iteration's top barrier orders stage reuse
    }

    #pragma unroll
    for (int mt = 0; mt < 4; mt++) {
        int r = brow + warp_m * 64 + mt * 16 + qr;
        #pragma unroll
        for (int nt = 0; nt < 4; nt++) {
            int c = bcol + warp_n * 32 + nt * 8 + qc * 2;
            if (r < M) {
                __half2 h = __floats2half2_rn(acc[mt][nt][0], acc[mt][nt][1]);
                *(__half2*)(C + (size_t)r * N + c) = h;
            }
            if (r + 8 < M) {
                __half2 h = __floats2half2_rn(acc[mt][nt][2], acc[mt][nt][3]);
                *(__half2*)(C + (size_t)(r + 8) * N + c) = h;
            }
        }
    }
}

// ---------------------------------------------------------------------------
// CSR-by-dst build
// ---------------------------------------------------------------------------
__global__ void hist_k(const int* __restrict__ ei, int* __restrict__ cnt) {
    int e = blockIdx.x * blockDim.x + threadIdx.x;
    if (e < N_EDGES) atomicAdd(&cnt[ei[N_EDGES + e]], 1);
}

__global__ __launch_bounds__(1024)
void scan_k(const int* __restrict__ cnt, int* __restrict__ off, int* __restrict__ cur) {
    __shared__ int sums[1024];
    const int t = threadIdx.x;
    const int CH = (N_NODES + 1023) / 1024;
    const int lo = t * CH;
    const int hi = min(lo + CH, N_NODES);
    int s = 0;
    for (int i = lo; i < hi; i++) s += cnt[i];
    sums[t] = s;
    __syncthreads();
    for (int d = 1; d < 1024; d <<= 1) {
        int v = (t >= d) ? sums[t - d] : 0;
        __syncthreads();
        sums[t] += v;
        __syncthreads();
    }
    int run = (t == 0) ? 0 : sums[t - 1];
    for (int i = lo; i < hi; i++) {
        off[i] = run; cur[i] = run;
        run += cnt[i];
    }
    if (t == 1023) off[N_NODES] = run;
}

__global__ void permute_k(const int* __restrict__ ei, const float* __restrict__ ew,
                          int* __restrict__ cur, int* __restrict__ psrc,
                          float* __restrict__ pw) {
    int e = blockIdx.x * blockDim.x + threadIdx.x;
    if (e >= N_EDGES) return;
    int dst = ei[N_EDGES + e];
    int pos = atomicAdd(&cur[dst], 1);
    psrc[pos] = ei[e];
    pw[pos]   = ew[e];
}

// ---------------------------------------------------------------------------
// Gather aggregation (warp per node), 4-edge unrolled, fused bias+relu.
// (R9 versions — proven best; R12 showed 2-warp split is neutral.)
// ---------------------------------------------------------------------------
__device__ __forceinline__ void acc8(float* acc, uint4 r, float w) {
    float2 f0 = __half22float2(*(__half2*)&r.x);
    float2 f1 = __half22float2(*(__half2*)&r.y);
    float2 f2 = __half22float2(*(__half2*)&r.z);
    float2 f3 = __half22float2(*(__half2*)&r.w);
    acc[0] += f0.x * w; acc[1] += f0.y * w;
    acc[2] += f1.x * w; acc[3] += f1.y * w;
    acc[4] += f2.x * w; acc[5] += f2.y * w;
    acc[6] += f3.x * w; acc[7] += f3.y * w;
}

__global__ __launch_bounds__(256)
void agg512_h(const __half* __restrict__ S, const int* __restrict__ off,
              const int* __restrict__ psrc, const float* __restrict__ pw,
              const float* __restrict__ bias, __half* __restrict__ outh) {
    const int node = (blockIdx.x * blockDim.x + threadIdx.x) >> 5;
    const int lane = threadIdx.x & 31;
    if (node >= N_NODES) return;
    const int e0 = off[node], e1 = off[node + 1];

    float acc[16];
    #pragma unroll
    for (int i = 0; i < 16; i++) acc[i] = 0.f;

    int e = e0;
    for (; e + 4 <= e1; e += 4) {
        int   s0 = psrc[e],   s1 = psrc[e+1], s2 = psrc[e+2], s3 = psrc[e+3];
        float w0 = pw[e],     w1 = pw[e+1],   w2 = pw[e+2],   w3 = pw[e+3];
        const uint4* r0 = (const uint4*)(S + (size_t)s0 * D_HID);
        const uint4* r1 = (const uint4*)(S + (size_t)s1 * D_HID);
        const uint4* r2 = (const uint4*)(S + (size_t)s2 * D_HID);
        const uint4* r3 = (const uint4*)(S + (size_t)s3 * D_HID);
        uint4 x0 = r0[lane],      y0 = r1[lane],      z0 = r2[lane],      u0 = r3[lane];
        uint4 x1 = r0[lane + 32], y1 = r1[lane + 32], z1 = r2[lane + 32], u1 = r3[lane + 32];
        acc8(acc, x0, w0); acc8(acc + 8, x1, w0);
        acc8(acc, y0, w1); acc8(acc + 8, y1, w1);
        acc8(acc, z0, w2); acc8(acc + 8, z1, w2);
        acc8(acc, u0, w3); acc8(acc + 8, u1, w3);
    }
    for (; e < e1; e++) {
        int s0 = psrc[e]; float w0 = pw[e];
        const uint4* r0 = (const uint4*)(S + (size_t)s0 * D_HID);
        uint4 x0 = r0[lane];
        uint4 x1 = r0[lane + 32];
        acc8(acc, x0, w0); acc8(acc + 8, x1, w0);
    }

    #pragma unroll
    for (int t = 0; t < 2; t++) {
        const int fb = (lane + t * 32) * 8;
        float4 b0 = *(const float4*)(bias + fb);
        float4 b1 = *(const float4*)(bias + fb + 4);
        float* a = acc + t * 8;
        __half2 h0 = __floats2half2_rn(fmaxf(a[0]+b0.x,0.f), fmaxf(a[1]+b0.y,0.f));
        __half2 h1 = __floats2half2_rn(fmaxf(a[2]+b0.z,0.f), fmaxf(a[3]+b0.w,0.f));
        __half2 h2 = __floats2half2_rn(fmaxf(a[4]+b1.x,0.f), fmaxf(a[5]+b1.y,0.f));
        __half2 h3 = __floats2half2_rn(fmaxf(a[6]+b1.z,0.f), fmaxf(a[7]+b1.w,0.f));
        uint4 o;
        o.x = *(uint32_t*)&h0; o.y = *(uint32_t*)&h1;
        o.z = *(uint32_t*)&h2; o.w = *(uint32_t*)&h3;
        *(uint4*)(outh + (size_t)node * D_HID + fb) = o;
    }
}

__global__ __launch_bounds__(256)
void agg256_f(const __half* __restrict__ S, const int* __restrict__ off,
              const int* __restrict__ psrc, const float* __restrict__ pw,
              const float* __restrict__ bias, float* __restrict__ outf) {
    const int node = (blockIdx.x * blockDim.x + threadIdx.x) >> 5;
    const int lane = threadIdx.x & 31;
    if (node >= N_NODES) return;
    const int e0 = off[node], e1 = off[node + 1];

    float acc[8];
    #pragma unroll
    for (int i = 0; i < 8; i++) acc[i] = 0.f;

    int e = e0;
    for (; e + 4 <= e1; e += 4) {
        int   s0 = psrc[e],   s1 = psrc[e+1], s2 = psrc[e+2], s3 = psrc[e+3];
        float w0 = pw[e],     w1 = pw[e+1],   w2 = pw[e+2],   w3 = pw[e+3];
        uint4 x = ((const uint4*)(S + (size_t)s0 * D_LAT))[lane];
        uint4 y = ((const uint4*)(S + (size_t)s1 * D_LAT))[lane];
        uint4 z = ((const uint4*)(S + (size_t)s2 * D_LAT))[lane];
        uint4 u = ((const uint4*)(S + (size_t)s3 * D_LAT))[lane];
        acc8(acc, x, w0); acc8(acc, y, w1); acc8(acc, z, w2); acc8(acc, u, w3);
    }
    for (; e < e1; e++) {
        uint4 x = ((const uint4*)(S + (size_t)psrc[e] * D_LAT))[lane];
        acc8(acc, x, pw[e]);
    }

    const int fb = lane * 8;
    float4 b0 = *(const float4*)(bias + fb);
    float4 b1 = *(const float4*)(bias + fb + 4);
    float4 o0 = make_float4(fmaxf(acc[0]+b0.x,0.f), fmaxf(acc[1]+b0.y,0.f),
                            fmaxf(acc[2]+b0.z,0.f), fmaxf(acc[3]+b0.w,0.f));
    float4 o1 = make_float4(fmaxf(acc[4]+b1.x,0.f), fmaxf(acc[5]+b1.y,0.f),
                            fmaxf(acc[6]+b1.z,0.f), fmaxf(acc[7]+b1.w,0.f));
    float* op = outf + (size_t)node * D_LAT + fb;
    *(float4*)op       = o0;
    *(float4*)(op + 4) = o1;
}

// ---------------------------------------------------------------------------
// staging
// ---------------------------------------------------------------------------
__global__ void to_half(const float4* __restrict__ in, uint2* __restrict__ out, int n4) {
    int i = blockIdx.x * blockDim.x + threadIdx.x;
    int stride = gridDim.x * blockDim.x;
    for (; i < n4; i += stride) {
        float4 v = in[i];
        __half2 h0 = __floats2half2_rn(v.x, v.y);
        __half2 h1 = __floats2half2_rn(v.z, v.w);
        out[i] = make_uint2(*(uint32_t*)&h0, *(uint32_t*)&h1);
    }
}

__global__ __launch_bounds__(256)
void transpose_h(const float* __restrict__ in, __half* __restrict__ out, int R, int Cc) {
    __shared__ float t[32][33];
    const int c0 = blockIdx.x * 32, r0 = blockIdx.y * 32;
    const int tx = threadIdx.x, ty = threadIdx.y;
    #pragma unroll
    for (int i = ty; i < 32; i += 8)
        t[i][tx] = in[(size_t)(r0 + i) * Cc + c0 + tx];
    __syncthreads();
    #pragma unroll
    for (int i = ty; i < 32; i += 8)
        out[(size_t)(c0 + i) * R + r0 + tx] = __float2half(t[tx][i]);
}

// ---------------------------------------------------------------------------
// launch — R9 topology (proven): single serial main chain, only the SM-light
// CSR branch forked.
// ---------------------------------------------------------------------------
extern "C" void kernel_launch(void* const* d_in, const int* in_sizes, int n_in,
                              void* d_out, int out_size) {
    const float* x  = (const float*)d_in[0];
    const int*   ei = (const int*)  d_in[1];
    const float* ew = (const float*)d_in[2];
    const float* W1 = (const float*)d_in[3];
    const float* b1 = (const float*)d_in[4];
    const float* W2 = (const float*)d_in[5];
    const float* b2 = (const float*)d_in[6];
    float* out = (float*)d_out;

    __half *s1h, *s2h, *xh, *hh, *w1t, *w2t;
    int *cnt, *off, *cur, *psrc;
    float *pw;
    cudaGetSymbolAddress((void**)&s1h,  g_s1h);
    cudaGetSymbolAddress((void**)&s2h,  g_s2h);
    cudaGetSymbolAddress((void**)&xh,   g_xh);
    cudaGetSymbolAddress((void**)&hh,   g_hh);
    cudaGetSymbolAddress((void**)&w1t,  g_w1t);
    cudaGetSymbolAddress((void**)&w2t,  g_w2t);
    cudaGetSymbolAddress((void**)&cnt,  g_cnt);
    cudaGetSymbolAddress((void**)&off,  g_off);
    cudaGetSymbolAddress((void**)&cur,  g_cur);
    cudaGetSymbolAddress((void**)&psrc, g_psrc);
    cudaGetSymbolAddress((void**)&pw,   g_pw);

    static cudaStream_t s2 = nullptr;
    static cudaEvent_t evA = nullptr, evB = nullptr;
    static bool init_done = false;
    if (!init_done) {
        cudaFuncSetAttribute(gemm_h, cudaFuncAttributeMaxDynamicSharedMemorySize,
                             SMEM_BYTES);
        cudaStreamCreateWithFlags(&s2, cudaStreamNonBlocking);
        cudaEventCreateWithFlags(&evA, cudaEventDisableTiming);
        cudaEventCreateWithFlags(&evB, cudaEventDisableTiming);
        init_done = true;
    }

    const int mblocks = (N_NODES + BM - 1) / BM;        // 391

    // fork: side branch (CSR build + W2 transpose) on s2
    cudaEventRecord(evA, 0);
    cudaStreamWaitEvent(s2, evA, 0);
    cudaMemsetAsync(cnt, 0, N_NODES * sizeof(int), s2);
    hist_k<<<(N_EDGES + 255) / 256, 256, 0, s2>>>(ei, cnt);
    scan_k<<<1, 1024, 0, s2>>>(cnt, off, cur);
    permute_k<<<(N_EDGES + 255) / 256, 256, 0, s2>>>(ei, ew, cur, psrc, pw);
    transpose_h<<<dim3(D_LAT / 32, D_HID / 32), dim3(32, 8), 0, s2>>>(W2, w2t,
                                                                      D_HID, D_LAT);
    cudaEventRecord(evB, s2);

    // main branch: staging + GEMM1
    to_half<<<4096, 256>>>((const float4*)x, (uint2*)xh, N_NODES * D_IN / 4);
    transpose_h<<<dim3(D_HID / 32, D_IN / 32), dim3(32, 8)>>>(W1, w1t, D_IN, D_HID);
    gemm_h<<<dim3(mblocks, D_HID / BN), 256, SMEM_BYTES>>>(xh, w1t, s1h,
                                                           N_NODES, D_HID, D_IN);

    // join: agg needs CSR arrays
    cudaStreamWaitEvent(0, evB, 0);
    const int agg_blocks = (N_NODES * 32 + 255) / 256;  // 6250
    agg512_h<<<agg_blocks, 256>>>(s1h, off, psrc, pw, b1, hh);

    // Layer 2
    gemm_h<<<dim3(mblocks, D_LAT / BN), 256, SMEM_BYTES>>>(hh, w2t, s2h,
                                                           N_NODES, D_LAT, D_HID);
    agg256_f<<<agg_blocks, 256>>>(s2h, off, psrc, pw, b2, out);
}

// round 14
// speedup vs baseline: 1.4287x; 1.0042x over previous
#include <cuda_runtime.h>
#include <cuda_fp16.h>
#include <cstdint>

#define N_NODES 50000
#define N_EDGES 400000
#define D_IN    1024
#define D_HID   512
#define D_LAT   256

// Scratch (allocation-free rule: __device__ globals)
__device__ __half g_s1h[(size_t)N_NODES * D_HID];   // x @ W1 (fp16, gather src)
__device__ __half g_s2h[(size_t)N_NODES * D_LAT];   // hh @ W2 (fp16, gather src)
__device__ __half g_xh [(size_t)N_NODES * D_IN];    // x in fp16
__device__ __half g_hh [(size_t)N_NODES * D_HID];   // relu(agg1+b1) fp16
__device__ __half g_w1t[(size_t)D_HID * D_IN];      // W1^T fp16 [N][K]
__device__ __half g_w2t[(size_t)D_LAT * D_HID];     // W2^T fp16 [N][K]
// CSR-by-dst build
__device__ int   g_cnt [N_NODES];
__device__ int   g_off [N_NODES + 1];
__device__ int   g_cur [N_NODES];
__device__ int   g_psrc[N_EDGES];
__device__ float g_pw  [N_EDGES];

// ---------------------------------------------------------------------------
// fp16 mma.sync GEMM (R13, proven): CTA 128x128, BK=64, 3-stage cp.async,
// 256 thr (8 warps, 64x32 warp tile), ldmatrix.x4, XOR swizzle, 2 CTAs/SM.
// ---------------------------------------------------------------------------
#define BM 128
#define BN 128
#define BK 64
#define STAGES 3
#define A_BYTES (BM * 128)
#define B_BYTES (BN * 128)
#define STAGE_BYTES (A_BYTES + B_BYTES)
#define SMEM_BYTES (STAGES * STAGE_BYTES)  // 98304

__device__ __forceinline__ void hmma(float c[4], const uint32_t a[4],
                                     uint32_t b0, uint32_t b1) {
    asm volatile(
        "mma.sync.aligned.m16n8k16.row.col.f32.f16.f16.f32 "
        "{%0,%1,%2,%3}, {%4,%5,%6,%7}, {%8,%9}, {%0,%1,%2,%3};"
        : "+f"(c[0]), "+f"(c[1]), "+f"(c[2]), "+f"(c[3])
        : "r"(a[0]), "r"(a[1]), "r"(a[2]), "r"(a[3]), "r"(b0), "r"(b1));
}

__device__ __forceinline__ void ldsm4(uint32_t r[4], uint32_t addr) {
    asm volatile("ldmatrix.sync.aligned.m8n8.x4.shared.b16 {%0,%1,%2,%3}, [%4];"
                 : "=r"(r[0]), "=r"(r[1]), "=r"(r[2]), "=r"(r[3]) : "r"(addr));
}

__device__ __forceinline__ void cp16(uint32_t dst, const void* src, int sz) {
    asm volatile("cp.async.ca.shared.global [%0], [%1], 16, %2;\n"
                 :: "r"(dst), "l"(src), "r"(sz));
}
__device__ __forceinline__ void cp16u(uint32_t dst, const void* src) {
    asm volatile("cp.async.ca.shared.global [%0], [%1], 16;\n"
                 :: "r"(dst), "l"(src));
}

__global__ __launch_bounds__(256, 2)
void gemm_h(const __half* __restrict__ A, const __half* __restrict__ Bt,
            __half* __restrict__ C, int M, int N, int K) {
    extern __shared__ uint32_t smem[];
    const uint32_t sbase = (uint32_t)__cvta_generic_to_shared(smem);

    const int tid  = threadIdx.x;
    const int lane = tid & 31;
    const int wid  = tid >> 5;
    const int warp_m = wid & 1;
    const int warp_n = wid >> 1;
    const int qr = lane >> 2;
    const int qc = lane & 3;
    const int brow = blockIdx.x * BM;
    const int bcol = blockIdx.y * BN;

    const int laneA_row = lane & 15;
    const int laneA_h   = lane >> 4;
    const int laneB_row = (lane & 7) + ((lane >> 4) << 3);
    const int laneB_h   = (lane >> 3) & 1;
    const int rowA_base = warp_m * 64 + laneA_row;
    const int rowB_base = warp_n * 32 + laneB_row;

    float acc[4][4][4];
    #pragma unroll
    for (int i = 0; i < 4; i++)
        #pragma unroll
        for (int j = 0; j < 4; j++)
            #pragma unroll
            for (int k = 0; k < 4; k++) acc[i][j][k] = 0.f;

    auto load_stage = [&](int kt, int s) {
        const int kb = kt * BK;
        const uint32_t ab = sbase + (uint32_t)s * STAGE_BYTES;
        const uint32_t bb = ab + A_BYTES;
        #pragma unroll
        for (int t = 0; t < 4; t++) {
            int idx = tid + t * 256;
            int r = idx >> 3, c = idx & 7;
            int gr = brow + r;
            uint32_t dst = ab + r * 128 + ((c ^ (r & 7)) << 4);
            cp16(dst, A + (size_t)gr * K + kb + c * 8, (gr < M) ? 16 : 0);
        }
        #pragma unroll
        for (int t = 0; t < 4; t++) {
            int idx = tid + t * 256;
            int r = idx >> 3, c = idx & 7;
            uint32_t dst = bb + r * 128 + ((c ^ (r & 7)) << 4);
            cp16u(dst, Bt + (size_t)(bcol + r) * K + kb + c * 8);
        }
    };

    const int nk = K / BK;
    #pragma unroll
    for (int i = 0; i < STAGES - 1; i++) {
        load_stage(i, i);
        asm volatile("cp.async.commit_group;\n");
    }

    for (int kt = 0; kt < nk; kt++) {
        asm volatile("cp.async.wait_group %0;\n" :: "n"(STAGES - 2));
        __syncthreads();

        if (kt + STAGES - 1 < nk) load_stage(kt + STAGES - 1, (kt + STAGES - 1) % STAGES);
        asm volatile("cp.async.commit_group;\n");

        const int s = kt % STAGES;
        const uint32_t Ab = sbase + (uint32_t)s * STAGE_BYTES;
        const uint32_t Bb = Ab + A_BYTES;

        #pragma unroll
        for (int ks = 0; ks < 4; ks++) {
            uint32_t a[4][4], b[2][4];
            #pragma unroll
            for (int mt = 0; mt < 4; mt++) {
                int row = rowA_base + mt * 16;
                int ch  = ks * 2 + laneA_h;
                ldsm4(a[mt], Ab + row * 128 + ((ch ^ (row & 7)) << 4));
            }
            #pragma unroll
            for (int np = 0; np < 2; np++) {
                int row = rowB_base + np * 16;
                int ch  = ks * 2 + laneB_h;
                ldsm4(b[np], Bb + row * 128 + ((ch ^ (row & 7)) << 4));
            }
            #pragma unroll
            for (int mt = 0; mt < 4; mt++)
                #pragma unroll
                for (int nt = 0; nt < 4; nt++)
                    hmma(acc[mt][nt], a[mt], b[nt >> 1][(nt & 1) * 2],
                                             b[nt >> 1][(nt & 1) * 2 + 1]);
        }
    }

    #pragma unroll
    for (int mt = 0; mt < 4; mt++) {
        int r = brow + warp_m * 64 + mt * 16 + qr;
        #pragma unroll
        for (int nt = 0; nt < 4; nt++) {
            int c = bcol + warp_n * 32 + nt * 8 + qc * 2;
            if (r < M) {
                __half2 h = __floats2half2_rn(acc[mt][nt][0], acc[mt][nt][1]);
                *(__half2*)(C + (size_t)r * N + c) = h;
            }
            if (r + 8 < M) {
                __half2 h = __floats2half2_rn(acc[mt][nt][2], acc[mt][nt][3]);
                *(__half2*)(C + (size_t)(r + 8) * N + c) = h;
            }
        }
    }
}

// ---------------------------------------------------------------------------
// CSR-by-dst build
// ---------------------------------------------------------------------------
__global__ void hist_k(const int* __restrict__ ei, int* __restrict__ cnt) {
    int e = blockIdx.x * blockDim.x + threadIdx.x;
    if (e < N_EDGES) atomicAdd(&cnt[ei[N_EDGES + e]], 1);
}

__global__ __launch_bounds__(1024)
void scan_k(const int* __restrict__ cnt, int* __restrict__ off, int* __restrict__ cur) {
    __shared__ int sums[1024];
    const int t = threadIdx.x;
    const int CH = (N_NODES + 1023) / 1024;
    const int lo = t * CH;
    const int hi = min(lo + CH, N_NODES);
    int s = 0;
    for (int i = lo; i < hi; i++) s += cnt[i];
    sums[t] = s;
    __syncthreads();
    for (int d = 1; d < 1024; d <<= 1) {
        int v = (t >= d) ? sums[t - d] : 0;
        __syncthreads();
        sums[t] += v;
        __syncthreads();
    }
    int run = (t == 0) ? 0 : sums[t - 1];
    for (int i = lo; i < hi; i++) {
        off[i] = run; cur[i] = run;
        run += cnt[i];
    }
    if (t == 1023) off[N_NODES] = run;
}

__global__ void permute_k(const int* __restrict__ ei, const float* __restrict__ ew,
                          int* __restrict__ cur, int* __restrict__ psrc,
                          float* __restrict__ pw) {
    int e = blockIdx.x * blockDim.x + threadIdx.x;
    if (e >= N_EDGES) return;
    int dst = ei[N_EDGES + e];
    int pos = atomicAdd(&cur[dst], 1);
    psrc[pos] = ei[e];
    pw[pos]   = ew[e];
}

// ---------------------------------------------------------------------------
// Gather aggregation, fused bias+relu.
// agg512: warp/node, 4-edge unroll (R9 proven). agg256: warp/node, 8-edge.
// ---------------------------------------------------------------------------
__device__ __forceinline__ void acc8(float* acc, uint4 r, float w) {
    float2 f0 = __half22float2(*(__half2*)&r.x);
    float2 f1 = __half22float2(*(__half2*)&r.y);
    float2 f2 = __half22float2(*(__half2*)&r.z);
    float2 f3 = __half22float2(*(__half2*)&r.w);
    acc[0] += f0.x * w; acc[1] += f0.y * w;
    acc[2] += f1.x * w; acc[3] += f1.y * w;
    acc[4] += f2.x * w; acc[5] += f2.y * w;
    acc[6] += f3.x * w; acc[7] += f3.y * w;
}

__global__ __launch_bounds__(256)
void agg512_h(const __half* __restrict__ S, const int* __restrict__ off,
              const int* __restrict__ psrc, const float* __restrict__ pw,
              const float* __restrict__ bias, __half* __restrict__ outh) {
    const int node = (blockIdx.x * blockDim.x + threadIdx.x) >> 5;
    const int lane = threadIdx.x & 31;
    if (node >= N_NODES) return;
    const int e0 = off[node], e1 = off[node + 1];

    float acc[16];
    #pragma unroll
    for (int i = 0; i < 16; i++) acc[i] = 0.f;

    int e = e0;
    for (; e + 4 <= e1; e += 4) {
        int   s0 = psrc[e],   s1 = psrc[e+1], s2 = psrc[e+2], s3 = psrc[e+3];
        float w0 = pw[e],     w1 = pw[e+1],   w2 = pw[e+2],   w3 = pw[e+3];
        const uint4* r0 = (const uint4*)(S + (size_t)s0 * D_HID);
        const uint4* r1 = (const uint4*)(S + (size_t)s1 * D_HID);
        const uint4* r2 = (const uint4*)(S + (size_t)s2 * D_HID);
        const uint4* r3 = (const uint4*)(S + (size_t)s3 * D_HID);
        uint4 x0 = r0[lane],      y0 = r1[lane],      z0 = r2[lane],      u0 = r3[lane];
        uint4 x1 = r0[lane + 32], y1 = r1[lane + 32], z1 = r2[lane + 32], u1 = r3[lane + 32];
        acc8(acc, x0, w0); acc8(acc + 8, x1, w0);
        acc8(acc, y0, w1); acc8(acc + 8, y1, w1);
        acc8(acc, z0, w2); acc8(acc + 8, z1, w2);
        acc8(acc, u0, w3); acc8(acc + 8, u1, w3);
    }
    for (; e < e1; e++) {
        int s0 = psrc[e]; float w0 = pw[e];
        const uint4* r0 = (const uint4*)(S + (size_t)s0 * D_HID);
        uint4 x0 = r0[lane];
        uint4 x1 = r0[lane + 32];
        acc8(acc, x0, w0); acc8(acc + 8, x1, w0);
    }

    #pragma unroll
    for (int t = 0; t < 2; t++) {
        const int fb = (lane + t * 32) * 8;
        float4 b0 = *(const float4*)(bias + fb);
        float4 b1 = *(const float4*)(bias + fb + 4);
        float* a = acc + t * 8;
        __half2 h0 = __floats2half2_rn(fmaxf(a[0]+b0.x,0.f), fmaxf(a[1]+b0.y,0.f));
        __half2 h1 = __floats2half2_rn(fmaxf(a[2]+b0.z,0.f), fmaxf(a[3]+b0.w,0.f));
        __half2 h2 = __floats2half2_rn(fmaxf(a[4]+b1.x,0.f), fmaxf(a[5]+b1.y,0.f));
        __half2 h3 = __floats2half2_rn(fmaxf(a[6]+b1.z,0.f), fmaxf(a[7]+b1.w,0.f));
        uint4 o;
        o.x = *(uint32_t*)&h0; o.y = *(uint32_t*)&h1;
        o.z = *(uint32_t*)&h2; o.w = *(uint32_t*)&h3;
        *(uint4*)(outh + (size_t)node * D_HID + fb) = o;
    }
}

__global__ __launch_bounds__(256)
void agg256_f(const __half* __restrict__ S, const int* __restrict__ off,
              const int* __restrict__ psrc, const float* __restrict__ pw,
              const float* __restrict__ bias, float* __restrict__ outf) {
    const int node = (blockIdx.x * blockDim.x + threadIdx.x) >> 5;
    const int lane = threadIdx.x & 31;
    if (node >= N_NODES) return;
    const int e0 = off[node], e1 = off[node + 1];

    float acc[8];
    #pragma unroll
    for (int i = 0; i < 8; i++) acc[i] = 0.f;

    int e = e0;
    for (; e + 8 <= e1; e += 8) {
        int   si[8]; float wi[8];
        #pragma unroll
        for (int j = 0; j < 8; j++) { si[j] = psrc[e + j]; wi[j] = pw[e + j]; }
        uint4 rv[8];
        #pragma unroll
        for (int j = 0; j < 8; j++)
            rv[j] = ((const uint4*)(S + (size_t)si[j] * D_LAT))[lane];
        #pragma unroll
        for (int j = 0; j < 8; j++) acc8(acc, rv[j], wi[j]);
    }
    for (; e + 4 <= e1; e += 4) {
        int   s0 = psrc[e],   s1 = psrc[e+1], s2 = psrc[e+2], s3 = psrc[e+3];
        float w0 = pw[e],     w1 = pw[e+1],   w2 = pw[e+2],   w3 = pw[e+3];
        uint4 x = ((const uint4*)(S + (size_t)s0 * D_LAT))[lane];
        uint4 y = ((const uint4*)(S + (size_t)s1 * D_LAT))[lane];
        uint4 z = ((const uint4*)(S + (size_t)s2 * D_LAT))[lane];
        uint4 u = ((const uint4*)(S + (size_t)s3 * D_LAT))[lane];
        acc8(acc, x, w0); acc8(acc, y, w1); acc8(acc, z, w2); acc8(acc, u, w3);
    }
    for (; e < e1; e++) {
        uint4 x = ((const uint4*)(S + (size_t)psrc[e] * D_LAT))[lane];
        acc8(acc, x, pw[e]);
    }

    const int fb = lane * 8;
    float4 b0 = *(const float4*)(bias + fb);
    float4 b1 = *(const float4*)(bias + fb + 4);
    float4 o0 = make_float4(fmaxf(acc[0]+b0.x,0.f), fmaxf(acc[1]+b0.y,0.f),
                            fmaxf(acc[2]+b0.z,0.f), fmaxf(acc[3]+b0.w,0.f));
    float4 o1 = make_float4(fmaxf(acc[4]+b1.x,0.f), fmaxf(acc[5]+b1.y,0.f),
                            fmaxf(acc[6]+b1.z,0.f), fmaxf(acc[7]+b1.w,0.f));
    float* op = outf + (size_t)node * D_LAT + fb;
    *(float4*)op       = o0;
    *(float4*)(op + 4) = o1;
}

// ---------------------------------------------------------------------------
// staging: fused x->fp16 convert + W1 transpose (one launch)
// blocks [0, CONV_BLOCKS): grid-stride convert; rest: 32x32 transpose tiles
// ---------------------------------------------------------------------------
#define CONV_BLOCKS 4096
#define W1T_BLOCKS ((D_HID / 32) * (D_IN / 32))   // 16 * 32 = 512

__global__ __launch_bounds__(256)
void stage_inputs(const float4* __restrict__ x4, uint2* __restrict__ xh8, int n4,
                  const float* __restrict__ W1, __half* __restrict__ w1t) {
    __shared__ float t[32][33];
    if (blockIdx.x < CONV_BLOCKS) {
        int i = blockIdx.x * 256 + threadIdx.x;
        const int stride = CONV_BLOCKS * 256;
        for (; i < n4; i += stride) {
            float4 v = x4[i];
            __half2 h0 = __floats2half2_rn(v.x, v.y);
            __half2 h1 = __floats2half2_rn(v.z, v.w);
            xh8[i] = make_uint2(*(uint32_t*)&h0, *(uint32_t*)&h1);
        }
    } else {
        const int b  = blockIdx.x - CONV_BLOCKS;
        const int c0 = (b % (D_HID / 32)) * 32;
        const int r0 = (b / (D_HID / 32)) * 32;
        const int tx = threadIdx.x & 31, ty = threadIdx.x >> 5;
        #pragma unroll
        for (int i = ty; i < 32; i += 8)
            t[i][tx] = W1[(size_t)(r0 + i) * D_HID + c0 + tx];
        __syncthreads();
        #pragma unroll
        for (int i = ty; i < 32; i += 8)
            w1t[(size_t)(c0 + i) * D_IN + r0 + tx] = __float2half(t[tx][i]);
    }
}

__global__ __launch_bounds__(256)
void transpose_h(const float* __restrict__ in, __half* __restrict__ out, int R, int Cc) {
    __shared__ float t[32][33];
    const int c0 = blockIdx.x * 32, r0 = blockIdx.y * 32;
    const int tx = threadIdx.x, ty = threadIdx.y;
    #pragma unroll
    for (int i = ty; i < 32; i += 8)
        t[i][tx] = in[(size_t)(r0 + i) * Cc + c0 + tx];
    __syncthreads();
    #pragma unroll
    for (int i = ty; i < 32; i += 8)
        out[(size_t)(c0 + i) * R + r0 + tx] = __float2half(t[tx][i]);
}

// ---------------------------------------------------------------------------
// launch — R13 topology (proven): serial main chain; SM-light CSR branch forked
// ---------------------------------------------------------------------------
extern "C" void kernel_launch(void* const* d_in, const int* in_sizes, int n_in,
                              void* d_out, int out_size) {
    const float* x  = (const float*)d_in[0];
    const int*   ei = (const int*)  d_in[1];
    const float* ew = (const float*)d_in[2];
    const float* W1 = (const float*)d_in[3];
    const float* b1 = (const float*)d_in[4];
    const float* W2 = (const float*)d_in[5];
    const float* b2 = (const float*)d_in[6];
    float* out = (float*)d_out;

    __half *s1h, *s2h, *xh, *hh, *w1t, *w2t;
    int *cnt, *off, *cur, *psrc;
    float *pw;
    cudaGetSymbolAddress((void**)&s1h,  g_s1h);
    cudaGetSymbolAddress((void**)&s2h,  g_s2h);
    cudaGetSymbolAddress((void**)&xh,   g_xh);
    cudaGetSymbolAddress((void**)&hh,   g_hh);
    cudaGetSymbolAddress((void**)&w1t,  g_w1t);
    cudaGetSymbolAddress((void**)&w2t,  g_w2t);
    cudaGetSymbolAddress((void**)&cnt,  g_cnt);
    cudaGetSymbolAddress((void**)&off,  g_off);
    cudaGetSymbolAddress((void**)&cur,  g_cur);
    cudaGetSymbolAddress((void**)&psrc, g_psrc);
    cudaGetSymbolAddress((void**)&pw,   g_pw);

    static cudaStream_t s2 = nullptr;
    static cudaEvent_t evA = nullptr, evB = nullptr;
    static bool init_done = false;
    if (!init_done) {
        cudaFuncSetAttribute(gemm_h, cudaFuncAttributeMaxDynamicSharedMemorySize,
                             SMEM_BYTES);
        cudaStreamCreateWithFlags(&s2, cudaStreamNonBlocking);
        cudaEventCreateWithFlags(&evA, cudaEventDisableTiming);
        cudaEventCreateWithFlags(&evB, cudaEventDisableTiming);
        init_done = true;
    }

    const int mblocks = (N_NODES + BM - 1) / BM;        // 391

    // fork: side branch (CSR build + W2 transpose) on s2
    cudaEventRecord(evA, 0);
    cudaStreamWaitEvent(s2, evA, 0);
    cudaMemsetAsync(cnt, 0, N_NODES * sizeof(int), s2);
    hist_k<<<(N_EDGES + 255) / 256, 256, 0, s2>>>(ei, cnt);
    scan_k<<<1, 1024, 0, s2>>>(cnt, off, cur);
    permute_k<<<(N_EDGES + 255) / 256, 256, 0, s2>>>(ei, ew, cur, psrc, pw);
    transpose_h<<<dim3(D_LAT / 32, D_HID / 32), dim3(32, 8), 0, s2>>>(W2, w2t,
                                                                      D_HID, D_LAT);
    cudaEventRecord(evB, s2);

    // main branch: fused staging (x convert + W1 transpose), then GEMM1
    stage_inputs<<<CONV_BLOCKS + W1T_BLOCKS, 256>>>(
        (const float4*)x, (uint2*)xh, N_NODES * D_IN / 4, W1, w1t);
    gemm_h<<<dim3(mblocks, D_HID / BN), 256, SMEM_BYTES>>>(xh, w1t, s1h,
                                                           N_NODES, D_HID, D_IN);

    // join: agg needs CSR arrays
    cudaStreamWaitEvent(0, evB, 0);
    const int agg_blocks = (N_NODES * 32 + 255) / 256;  // 6250
    agg512_h<<<agg_blocks, 256>>>(s1h, off, psrc, pw, b1, hh);

    // Layer 2
    gemm_h<<<dim3(mblocks, D_LAT / BN), 256, SMEM_BYTES>>>(hh, w2t, s2h,
                                                           N_NODES, D_LAT, D_HID);
    agg256_f<<<agg_blocks, 256>>>(s2h, off, psrc, pw, b2, out);
}

// round 15
// speedup vs baseline: 1.4411x; 1.0087x over previous
#include <cuda_runtime.h>
#include <cuda_fp16.h>
#include <cstdint>

#define N_NODES 50000
#define N_EDGES 400000
#define D_IN    1024
#define D_HID   512
#define D_LAT   256

// Scratch (allocation-free rule: __device__ globals)
__device__ __half g_s1h[(size_t)N_NODES * D_HID];   // x @ W1 (fp16, gather src)
__device__ __half g_s2h[(size_t)N_NODES * D_LAT];   // hh @ W2 (fp16, gather src)
__device__ __half g_xh [(size_t)N_NODES * D_IN];    // x in fp16
__device__ __half g_hh [(size_t)N_NODES * D_HID];   // relu(agg1+b1) fp16
__device__ __half g_w1t[(size_t)D_HID * D_IN];      // W1^T fp16 [N][K]
__device__ __half g_w2t[(size_t)D_LAT * D_HID];     // W2^T fp16 [N][K]
// CSR-by-dst build
__device__ int   g_cnt [N_NODES];
__device__ int   g_off [N_NODES + 1];
__device__ int   g_cur [N_NODES];
__device__ int   g_psrc[N_EDGES];
__device__ float g_pw  [N_EDGES];

// ---------------------------------------------------------------------------
// fp16 mma.sync GEMM: CTA 128x128, BK=64, 3-stage cp.async, 256 thr (8 warps,
// 64x32 warp tile), ldmatrix.x4, XOR swizzle, 2 CTAs/SM.
// Mainloop software-pipelines A fragments: ldsm a[mt+1] issues before the
// HMMA group consuming a[mt], hiding LDSM return latency.
// ---------------------------------------------------------------------------
#define BM 128
#define BN 128
#define BK 64
#define STAGES 3
#define A_BYTES (BM * 128)
#define B_BYTES (BN * 128)
#define STAGE_BYTES (A_BYTES + B_BYTES)
#define SMEM_BYTES (STAGES * STAGE_BYTES)  // 98304

__device__ __forceinline__ void hmma(float c[4], const uint32_t a[4],
                                     uint32_t b0, uint32_t b1) {
    asm volatile(
        "mma.sync.aligned.m16n8k16.row.col.f32.f16.f16.f32 "
        "{%0,%1,%2,%3}, {%4,%5,%6,%7}, {%8,%9}, {%0,%1,%2,%3};"
        : "+f"(c[0]), "+f"(c[1]), "+f"(c[2]), "+f"(c[3])
        : "r"(a[0]), "r"(a[1]), "r"(a[2]), "r"(a[3]), "r"(b0), "r"(b1));
}

__device__ __forceinline__ void ldsm4(uint32_t r[4], uint32_t addr) {
    asm volatile("ldmatrix.sync.aligned.m8n8.x4.shared.b16 {%0,%1,%2,%3}, [%4];"
                 : "=r"(r[0]), "=r"(r[1]), "=r"(r[2]), "=r"(r[3]) : "r"(addr));
}

__device__ __forceinline__ void cp16(uint32_t dst, const void* src, int sz) {
    asm volatile("cp.async.ca.shared.global [%0], [%1], 16, %2;\n"
                 :: "r"(dst), "l"(src), "r"(sz));
}
__device__ __forceinline__ void cp16u(uint32_t dst, const void* src) {
    asm volatile("cp.async.ca.shared.global [%0], [%1], 16;\n"
                 :: "r"(dst), "l"(src));
}

__global__ __launch_bounds__(256, 2)
void gemm_h(const __half* __restrict__ A, const __half* __restrict__ Bt,
            __half* __restrict__ C, int M, int N, int K) {
    extern __shared__ uint32_t smem[];
    const uint32_t sbase = (uint32_t)__cvta_generic_to_shared(smem);

    const int tid  = threadIdx.x;
    const int lane = tid & 31;
    const int wid  = tid >> 5;
    const int warp_m = wid & 1;
    const int warp_n = wid >> 1;
    const int qr = lane >> 2;
    const int qc = lane & 3;
    const int brow = blockIdx.x * BM;
    const int bcol = blockIdx.y * BN;

    const int laneA_row = lane & 15;
    const int laneA_h   = lane >> 4;
    const int laneB_row = (lane & 7) + ((lane >> 4) << 3);
    const int laneB_h   = (lane >> 3) & 1;
    const int rowA_base = warp_m * 64 + laneA_row;
    const int rowB_base = warp_n * 32 + laneB_row;

    float acc[4][4][4];
    #pragma unroll
    for (int i = 0; i < 4; i++)
        #pragma unroll
        for (int j = 0; j < 4; j++)
            #pragma unroll
            for (int k = 0; k < 4; k++) acc[i][j][k] = 0.f;

    auto load_stage = [&](int kt, int s) {
        const int kb = kt * BK;
        const uint32_t ab = sbase + (uint32_t)s * STAGE_BYTES;
        const uint32_t bb = ab + A_BYTES;
        #pragma unroll
        for (int t = 0; t < 4; t++) {
            int idx = tid + t * 256;
            int r = idx >> 3, c = idx & 7;
            int gr = brow + r;
            uint32_t dst = ab + r * 128 + ((c ^ (r & 7)) << 4);
            cp16(dst, A + (size_t)gr * K + kb + c * 8, (gr < M) ? 16 : 0);
        }
        #pragma unroll
        for (int t = 0; t < 4; t++) {
            int idx = tid + t * 256;
            int r = idx >> 3, c = idx & 7;
            uint32_t dst = bb + r * 128 + ((c ^ (r & 7)) << 4);
            cp16u(dst, Bt + (size_t)(bcol + r) * K + kb + c * 8);
        }
    };

    const int nk = K / BK;
    #pragma unroll
    for (int i = 0; i < STAGES - 1; i++) {
        load_stage(i, i);
        asm volatile("cp.async.commit_group;\n");
    }

    for (int kt = 0; kt < nk; kt++) {
        asm volatile("cp.async.wait_group %0;\n" :: "n"(STAGES - 2));
        __syncthreads();

        if (kt + STAGES - 1 < nk) load_stage(kt + STAGES - 1, (kt + STAGES - 1) % STAGES);
        asm volatile("cp.async.commit_group;\n");

        const int s = kt % STAGES;
        const uint32_t Ab = sbase + (uint32_t)s * STAGE_BYTES;
        const uint32_t Bb = Ab + A_BYTES;

        #pragma unroll
        for (int ks = 0; ks < 4; ks++) {
            uint32_t b[2][4];
            #pragma unroll
            for (int np = 0; np < 2; np++) {
                int row = rowB_base + np * 16;
                int ch  = ks * 2 + laneB_h;
                ldsm4(b[np], Bb + row * 128 + ((ch ^ (row & 7)) << 4));
            }
            const int chA = ks * 2 + laneA_h;
            uint32_t a_cur[4], a_nxt[4];
            {
                int row = rowA_base;
                ldsm4(a_cur, Ab + row * 128 + ((chA ^ (row & 7)) << 4));
            }
            #pragma unroll
            for (int mt = 0; mt < 4; mt++) {
                if (mt < 3) {
                    int row = rowA_base + (mt + 1) * 16;
                    ldsm4(a_nxt, Ab + row * 128 + ((chA ^ (row & 7)) << 4));
                }
                #pragma unroll
                for (int nt = 0; nt < 4; nt++)
                    hmma(acc[mt][nt], a_cur, b[nt >> 1][(nt & 1) * 2],
                                             b[nt >> 1][(nt & 1) * 2 + 1]);
                #pragma unroll
                for (int j = 0; j < 4; j++) a_cur[j] = a_nxt[j];
            }
        }
    }

    #pragma unroll
    for (int mt = 0; mt < 4; mt++) {
        int r = brow + warp_m * 64 + mt * 16 + qr;
        #pragma unroll
        for (int nt = 0; nt < 4; nt++) {
            int c = bcol + warp_n * 32 + nt * 8 + qc * 2;
            if (r < M) {
                __half2 h = __floats2half2_rn(acc[mt][nt][0], acc[mt][nt][1]);
                *(__half2*)(C + (size_t)r * N + c) = h;
            }
            if (r + 8 < M) {
                __half2 h = __floats2half2_rn(acc[mt][nt][2], acc[mt][nt][3]);
                *(__half2*)(C + (size_t)(r + 8) * N + c) = h;
            }
        }
    }
}

// ---------------------------------------------------------------------------
// CSR-by-dst build
// ---------------------------------------------------------------------------
__global__ void hist_k(const int* __restrict__ ei, int* __restrict__ cnt) {
    int e = blockIdx.x * blockDim.x + threadIdx.x;
    if (e < N_EDGES) atomicAdd(&cnt[ei[N_EDGES + e]], 1);
}

__global__ __launch_bounds__(1024)
void scan_k(const int* __restrict__ cnt, int* __restrict__ off, int* __restrict__ cur) {
    __shared__ int sums[1024];
    const int t = threadIdx.x;
    const int CH = (N_NODES + 1023) / 1024;
    const int lo = t * CH;
    const int hi = min(lo + CH, N_NODES);
    int s = 0;
    for (int i = lo; i < hi; i++) s += cnt[i];
    sums[t] = s;
    __syncthreads();
    for (int d = 1; d < 1024; d <<= 1) {
        int v = (t >= d) ? sums[t - d] : 0;
        __syncthreads();
        sums[t] += v;
        __syncthreads();
    }
    int run = (t == 0) ? 0 : sums[t - 1];
    for (int i = lo; i < hi; i++) {
        off[i] = run; cur[i] = run;
        run += cnt[i];
    }
    if (t == 1023) off[N_NODES] = run;
}

__global__ void permute_k(const int* __restrict__ ei, const float* __restrict__ ew,
                          int* __restrict__ cur, int* __restrict__ psrc,
                          float* __restrict__ pw) {
    int e = blockIdx.x * blockDim.x + threadIdx.x;
    if (e >= N_EDGES) return;
    int dst = ei[N_EDGES + e];
    int pos = atomicAdd(&cur[dst], 1);
    psrc[pos] = ei[e];
    pw[pos]   = ew[e];
}

// ---------------------------------------------------------------------------
// Gather aggregation, fused bias+relu (R14 versions).
// ---------------------------------------------------------------------------
__device__ __forceinline__ void acc8(float* acc, uint4 r, float w) {
    float2 f0 = __half22float2(*(__half2*)&r.x);
    float2 f1 = __half22float2(*(__half2*)&r.y);
    float2 f2 = __half22float2(*(__half2*)&r.z);
    float2 f3 = __half22float2(*(__half2*)&r.w);
    acc[0] += f0.x * w; acc[1] += f0.y * w;
    acc[2] += f1.x * w; acc[3] += f1.y * w;
    acc[4] += f2.x * w; acc[5] += f2.y * w;
    acc[6] += f3.x * w; acc[7] += f3.y * w;
}

__global__ __launch_bounds__(256)
void agg512_h(const __half* __restrict__ S, const int* __restrict__ off,
              const int* __restrict__ psrc, const float* __restrict__ pw,
              const float* __restrict__ bias, __half* __restrict__ outh) {
    const int node = (blockIdx.x * blockDim.x + threadIdx.x) >> 5;
    const int lane = threadIdx.x & 31;
    if (node >= N_NODES) return;
    const int e0 = off[node], e1 = off[node + 1];

    float acc[16];
    #pragma unroll
    for (int i = 0; i < 16; i++) acc[i] = 0.f;

    int e = e0;
    for (; e + 4 <= e1; e += 4) {
        int   s0 = psrc[e],   s1 = psrc[e+1], s2 = psrc[e+2], s3 = psrc[e+3];
        float w0 = pw[e],     w1 = pw[e+1],   w2 = pw[e+2],   w3 = pw[e+3];
        const uint4* r0 = (const uint4*)(S + (size_t)s0 * D_HID);
        const uint4* r1 = (const uint4*)(S + (size_t)s1 * D_HID);
        const uint4* r2 = (const uint4*)(S + (size_t)s2 * D_HID);
        const uint4* r3 = (const uint4*)(S + (size_t)s3 * D_HID);
        uint4 x0 = r0[lane],      y0 = r1[lane],      z0 = r2[lane],      u0 = r3[lane];
        uint4 x1 = r0[lane + 32], y1 = r1[lane + 32], z1 = r2[lane + 32], u1 = r3[lane + 32];
        acc8(acc, x0, w0); acc8(acc + 8, x1, w0);
        acc8(acc, y0, w1); acc8(acc + 8, y1, w1);
        acc8(acc, z0, w2); acc8(acc + 8, z1, w2);
        acc8(acc, u0, w3); acc8(acc + 8, u1, w3);
    }
    for (; e < e1; e++) {
        int s0 = psrc[e]; float w0 = pw[e];
        const uint4* r0 = (const uint4*)(S + (size_t)s0 * D_HID);
        uint4 x0 = r0[lane];
        uint4 x1 = r0[lane + 32];
        acc8(acc, x0, w0); acc8(acc + 8, x1, w0);
    }

    #pragma unroll
    for (int t = 0; t < 2; t++) {
        const int fb = (lane + t * 32) * 8;
        float4 b0 = *(const float4*)(bias + fb);
        float4 b1 = *(const float4*)(bias + fb + 4);
        float* a = acc + t * 8;
        __half2 h0 = __floats2half2_rn(fmaxf(a[0]+b0.x,0.f), fmaxf(a[1]+b0.y,0.f));
        __half2 h1 = __floats2half2_rn(fmaxf(a[2]+b0.z,0.f), fmaxf(a[3]+b0.w,0.f));
        __half2 h2 = __floats2half2_rn(fmaxf(a[4]+b1.x,0.f), fmaxf(a[5]+b1.y,0.f));
        __half2 h3 = __floats2half2_rn(fmaxf(a[6]+b1.z,0.f), fmaxf(a[7]+b1.w,0.f));
        uint4 o;
        o.x = *(uint32_t*)&h0; o.y = *(uint32_t*)&h1;
        o.z = *(uint32_t*)&h2; o.w = *(uint32_t*)&h3;
        *(uint4*)(outh + (size_t)node * D_HID + fb) = o;
    }
}

__global__ __launch_bounds__(256)
void agg256_f(const __half* __restrict__ S, const int* __restrict__ off,
              const int* __restrict__ psrc, const float* __restrict__ pw,
              const float* __restrict__ bias, float* __restrict__ outf) {
    const int node = (blockIdx.x * blockDim.x + threadIdx.x) >> 5;
    const int lane = threadIdx.x & 31;
    if (node >= N_NODES) return;
    const int e0 = off[node], e1 = off[node + 1];

    float acc[8];
    #pragma unroll
    for (int i = 0; i < 8; i++) acc[i] = 0.f;

    int e = e0;
    for (; e + 8 <= e1; e += 8) {
        int   si[8]; float wi[8];
        #pragma unroll
        for (int j = 0; j < 8; j++) { si[j] = psrc[e + j]; wi[j] = pw[e + j]; }
        uint4 rv[8];
        #pragma unroll
        for (int j = 0; j < 8; j++)
            rv[j] = ((const uint4*)(S + (size_t)si[j] * D_LAT))[lane];
        #pragma unroll
        for (int j = 0; j < 8; j++) acc8(acc, rv[j], wi[j]);
    }
    for (; e + 4 <= e1; e += 4) {
        int   s0 = psrc[e],   s1 = psrc[e+1], s2 = psrc[e+2], s3 = psrc[e+3];
        float w0 = pw[e],     w1 = pw[e+1],   w2 = pw[e+2],   w3 = pw[e+3];
        uint4 x = ((const uint4*)(S + (size_t)s0 * D_LAT))[lane];
        uint4 y = ((const uint4*)(S + (size_t)s1 * D_LAT))[lane];
        uint4 z = ((const uint4*)(S + (size_t)s2 * D_LAT))[lane];
        uint4 u = ((const uint4*)(S + (size_t)s3 * D_LAT))[lane];
        acc8(acc, x, w0); acc8(acc, y, w1); acc8(acc, z, w2); acc8(acc, u, w3);
    }
    for (; e < e1; e++) {
        uint4 x = ((const uint4*)(S + (size_t)psrc[e] * D_LAT))[lane];
        acc8(acc, x, pw[e]);
    }

    const int fb = lane * 8;
    float4 b0 = *(const float4*)(bias + fb);
    float4 b1 = *(const float4*)(bias + fb + 4);
    float4 o0 = make_float4(fmaxf(acc[0]+b0.x,0.f), fmaxf(acc[1]+b0.y,0.f),
                            fmaxf(acc[2]+b0.z,0.f), fmaxf(acc[3]+b0.w,0.f));
    float4 o1 = make_float4(fmaxf(acc[4]+b1.x,0.f), fmaxf(acc[5]+b1.y,0.f),
                            fmaxf(acc[6]+b1.z,0.f), fmaxf(acc[7]+b1.w,0.f));
    float* op = outf + (size_t)node * D_LAT + fb;
    *(float4*)op       = o0;
    *(float4*)(op + 4) = o1;
}

// ---------------------------------------------------------------------------
// staging: fused x->fp16 convert + W1 transpose (one launch)
// ---------------------------------------------------------------------------
#define CONV_BLOCKS 4096
#define W1T_BLOCKS ((D_HID / 32) * (D_IN / 32))   // 512

__global__ __launch_bounds__(256)
void stage_inputs(const float4* __restrict__ x4, uint2* __restrict__ xh8, int n4,
                  const float* __restrict__ W1, __half* __restrict__ w1t) {
    __shared__ float t[32][33];
    if (blockIdx.x < CONV_BLOCKS) {
        int i = blockIdx.x * 256 + threadIdx.x;
        const int stride = CONV_BLOCKS * 256;
        for (; i < n4; i += stride) {
            float4 v = x4[i];
            __half2 h0 = __floats2half2_rn(v.x, v.y);
            __half2 h1 = __floats2half2_rn(v.z, v.w);
            xh8[i] = make_uint2(*(uint32_t*)&h0, *(uint32_t*)&h1);
        }
    } else {
        const int b  = blockIdx.x - CONV_BLOCKS;
        const int c0 = (b % (D_HID / 32)) * 32;
        const int r0 = (b / (D_HID / 32)) * 32;
        const int tx = threadIdx.x & 31, ty = threadIdx.x >> 5;
        #pragma unroll
        for (int i = ty; i < 32; i += 8)
            t[i][tx] = W1[(size_t)(r0 + i) * D_HID + c0 + tx];
        __syncthreads();
        #pragma unroll
        for (int i = ty; i < 32; i += 8)
            w1t[(size_t)(c0 + i) * D_IN + r0 + tx] = __float2half(t[tx][i]);
    }
}

__global__ __launch_bounds__(256)
void transpose_h(const float* __restrict__ in, __half* __restrict__ out, int R, int Cc) {
    __shared__ float t[32][33];
    const int c0 = blockIdx.x * 32, r0 = blockIdx.y * 32;
    const int tx = threadIdx.x, ty = threadIdx.y;
    #pragma unroll
    for (int i = ty; i < 32; i += 8)
        t[i][tx] = in[(size_t)(r0 + i) * Cc + c0 + tx];
    __syncthreads();
    #pragma unroll
    for (int i = ty; i < 32; i += 8)
        out[(size_t)(c0 + i) * R + r0 + tx] = __float2half(t[tx][i]);
}

// ---------------------------------------------------------------------------
// launch — R13/R14 topology (proven): serial main chain; CSR branch forked
// ---------------------------------------------------------------------------
extern "C" void kernel_launch(void* const* d_in, const int* in_sizes, int n_in,
                              void* d_out, int out_size) {
    const float* x  = (const float*)d_in[0];
    const int*   ei = (const int*)  d_in[1];
    const float* ew = (const float*)d_in[2];
    const float* W1 = (const float*)d_in[3];
    const float* b1 = (const float*)d_in[4];
    const float* W2 = (const float*)d_in[5];
    const float* b2 = (const float*)d_in[6];
    float* out = (float*)d_out;

    __half *s1h, *s2h, *xh, *hh, *w1t, *w2t;
    int *cnt, *off, *cur, *psrc;
    float *pw;
    cudaGetSymbolAddress((void**)&s1h,  g_s1h);
    cudaGetSymbolAddress((void**)&s2h,  g_s2h);
    cudaGetSymbolAddress((void**)&xh,   g_xh);
    cudaGetSymbolAddress((void**)&hh,   g_hh);
    cudaGetSymbolAddress((void**)&w1t,  g_w1t);
    cudaGetSymbolAddress((void**)&w2t,  g_w2t);
    cudaGetSymbolAddress((void**)&cnt,  g_cnt);
    cudaGetSymbolAddress((void**)&off,  g_off);
    cudaGetSymbolAddress((void**)&cur,  g_cur);
    cudaGetSymbolAddress((void**)&psrc, g_psrc);
    cudaGetSymbolAddress((void**)&pw,   g_pw);

    static cudaStream_t s2 = nullptr;
    static cudaEvent_t evA = nullptr, evB = nullptr;
    static bool init_done = false;
    if (!init_done) {
        cudaFuncSetAttribute(gemm_h, cudaFuncAttributeMaxDynamicSharedMemorySize,
                             SMEM_BYTES);
        cudaStreamCreateWithFlags(&s2, cudaStreamNonBlocking);
        cudaEventCreateWithFlags(&evA, cudaEventDisableTiming);
        cudaEventCreateWithFlags(&evB, cudaEventDisableTiming);
        init_done = true;
    }

    const int mblocks = (N_NODES + BM - 1) / BM;        // 391

    // fork: side branch (CSR build + W2 transpose) on s2
    cudaEventRecord(evA, 0);
    cudaStreamWaitEvent(s2, evA, 0);
    cudaMemsetAsync(cnt, 0, N_NODES * sizeof(int), s2);
    hist_k<<<(N_EDGES + 255) / 256, 256, 0, s2>>>(ei, cnt);
    scan_k<<<1, 1024, 0, s2>>>(cnt, off, cur);
    permute_k<<<(N_EDGES + 255) / 256, 256, 0, s2>>>(ei, ew, cur, psrc, pw);
    transpose_h<<<dim3(D_LAT / 32, D_HID / 32), dim3(32, 8), 0, s2>>>(W2, w2t,
                                                                      D_HID, D_LAT);
    cudaEventRecord(evB, s2);

    // main branch: fused staging (x convert + W1 transpose), then GEMM1
    stage_inputs<<<CONV_BLOCKS + W1T_BLOCKS, 256>>>(
        (const float4*)x, (uint2*)xh, N_NODES * D_IN / 4, W1, w1t);
    gemm_h<<<dim3(mblocks, D_HID / BN), 256, SMEM_BYTES>>>(xh, w1t, s1h,
                                                           N_NODES, D_HID, D_IN);

    // join: agg needs CSR arrays
    cudaStreamWaitEvent(0, evB, 0);
    const int agg_blocks = (N_NODES * 32 + 255) / 256;  // 6250
    agg512_h<<<agg_blocks, 256>>>(s1h, off, psrc, pw, b1, hh);

    // Layer 2
    gemm_h<<<dim3(mblocks, D_LAT / BN), 256, SMEM_BYTES>>>(hh, w2t, s2h,
                                                           N_NODES, D_LAT, D_HID);
    agg256_f<<<agg_blocks, 256>>>(s2h, off, psrc, pw, b2, out);
}